// round 14
// baseline (speedup 1.0000x reference)
#include <cuda_runtime.h>
#include <cuda_fp16.h>
#include <math.h>
#include <stdint.h>

#define NW   512
#define CDIM 256
#define PDIM 128
#define WSZ  (CDIM*PDIM)

// ---------------- scratch (static device globals; no allocations) ----------
__device__ float g_tgt [NW*WSZ];
__device__ float g_tgt2[NW*WSZ];
__device__ float g_tgt3[NW*WSZ];
__device__ __half g_memh[NW*WSZ];
__device__ __half g_tgth[NW*WSZ];
__device__ __half g_qh [NW*WSZ];
__device__ __half g_kh [NW*WSZ];
__device__ __half g_vh [NW*WSZ];
__device__ __half g_hh [NW*2*WSZ];
__device__ __half g_wh[2*458752];
__device__ float g_p0[NW*128];
__device__ float g_p1[NW*16];
__device__ float g_p2[NW*16];
__device__ float g_p3[NW*16];

// ================= helpers =================================================
__device__ __forceinline__ uint32_t smem_u32(const void* p) {
    uint32_t a;
    asm("{ .reg .u64 t; cvta.to.shared.u64 t, %1; cvt.u32.u64 %0, t; }" : "=r"(a) : "l"(p));
    return a;
}
#define LDSM_X4(r0,r1,r2,r3,addr) \
    asm volatile("ldmatrix.sync.aligned.m8n8.x4.shared.b16 {%0,%1,%2,%3}, [%4];" \
        : "=r"(r0),"=r"(r1),"=r"(r2),"=r"(r3) : "r"(addr))
#define LDSM_X4_T(r0,r1,r2,r3,addr) \
    asm volatile("ldmatrix.sync.aligned.m8n8.x4.trans.shared.b16 {%0,%1,%2,%3}, [%4];" \
        : "=r"(r0),"=r"(r1),"=r"(r2),"=r"(r3) : "r"(addr))
__device__ __forceinline__ void mma_f16(float* d, const unsigned* a, const unsigned* b) {
    asm volatile("mma.sync.aligned.m16n8k16.row.col.f32.f16.f16.f32 "
        "{%0,%1,%2,%3}, {%4,%5,%6,%7}, {%8,%9}, {%0,%1,%2,%3};"
        : "+f"(d[0]),"+f"(d[1]),"+f"(d[2]),"+f"(d[3])
        : "r"(a[0]),"r"(a[1]),"r"(a[2]),"r"(a[3]), "r"(b[0]),"r"(b[1]));
}
#define CP_ASYNC16(sa, gp) \
    asm volatile("cp.async.cg.shared.global [%0], [%1], 16;" :: "r"(sa), "l"(gp))
#define CP_COMMIT() asm volatile("cp.async.commit_group;" ::: "memory")
#define CP_WAIT0()  asm volatile("cp.async.wait_group 0;" ::: "memory")
__device__ __forceinline__ unsigned pack2h(float a, float b) {
    __half ah = __float2half_rn(a), bh = __float2half_rn(b);
    return (unsigned)__half_as_ushort(ah) | ((unsigned)__half_as_ushort(bh) << 16);
}
__device__ __forceinline__ void read_stats(const float* part, int win, int pstride, int nparts,
                                           float& mean, float& rstd) {
    float S = 0.f, Q = 0.f;
    for (int i = 0; i < nparts; ++i) { S += part[win*pstride + i*2]; Q += part[win*pstride + i*2 + 1]; }
    mean = S * (1.f / 32768.f);
    float var = Q * (1.f / 32768.f) - mean * mean;
    rstd = rsqrtf(var + 1e-5f);
}

// ---- shuffle-stencil GN+mix body for one 32-channel slice ----
__device__ __forceinline__ void gn_mix_slice(
        int win, int yb, int lane, int wid, float mean, float rstd,
        const float* __restrict__ in, const float* __restrict__ basep,
        const float* __restrict__ gw, const float* __restrict__ gb,
        const float* __restrict__ ls, float* __restrict__ outf,
        float& s2, float& q2, bool want_stats) {
    int p0 = lane * 4;
    int y = lane >> 2, x0 = (lane & 3) * 4;
    float vcnt = 3.f - (y == 0 ? 1.f : 0.f) - (y == 7 ? 1.f : 0.f);
    float rinv[4];
#pragma unroll
    for (int j = 0; j < 4; ++j) {
        int x = x0 + j;
        float hc = 3.f - (x == 0 ? 1.f : 0.f) - (x == 15 ? 1.f : 0.f);
        rinv[j] = 1.f / (hc * vcnt);
    }
#pragma unroll
    for (int ci = 0; ci < 4; ++ci) {
        int c = yb * 32 + wid * 4 + ci;
        size_t gi = (size_t)win * WSZ + c * 128 + p0;
        float w = gw[c], bb = gb[c];
        float4 v = *(const float4*)(in + gi);
        v.x = (v.x - mean) * rstd * w + bb;
        v.y = (v.y - mean) * rstd * w + bb;
        v.z = (v.z - mean) * rstd * w + bb;
        v.w = (v.w - mean) * rstd * w + bb;
        float L = __shfl_up_sync(0xffffffffu, v.w, 1);
        float R = __shfl_down_sync(0xffffffffu, v.x, 1);
        if (x0 == 0)  L = 0.f;
        if (x0 == 12) R = 0.f;
        float4 h;
        h.x = L + v.x + v.y;
        h.y = v.x + v.y + v.z;
        h.z = v.y + v.z + v.w;
        h.w = v.z + v.w + R;
        float4 up, dn;
        up.x = __shfl_up_sync(0xffffffffu, h.x, 4);
        up.y = __shfl_up_sync(0xffffffffu, h.y, 4);
        up.z = __shfl_up_sync(0xffffffffu, h.z, 4);
        up.w = __shfl_up_sync(0xffffffffu, h.w, 4);
        dn.x = __shfl_down_sync(0xffffffffu, h.x, 4);
        dn.y = __shfl_down_sync(0xffffffffu, h.y, 4);
        dn.z = __shfl_down_sync(0xffffffffu, h.z, 4);
        dn.w = __shfl_down_sync(0xffffffffu, h.w, 4);
        if (y == 0) { up.x = up.y = up.z = up.w = 0.f; }
        if (y == 7) { dn.x = dn.y = dn.z = dn.w = 0.f; }
        float o0 = (up.x + h.x + dn.x) * rinv[0] - v.x;
        float o1 = (up.y + h.y + dn.y) * rinv[1] - v.y;
        float o2 = (up.z + h.z + dn.z) * rinv[2] - v.z;
        float o3 = (up.w + h.w + dn.w) * rinv[3] - v.w;
        float4 bv = *(const float4*)(basep + gi);
        float lsv = ls[c];
        float4 ov = {bv.x + lsv * o0, bv.y + lsv * o1,
                     bv.z + lsv * o2, bv.w + lsv * o3};
        *(float4*)(outf + gi) = ov;
        if (want_stats) {
            s2 += ov.x + ov.y + ov.z + ov.w;
            q2 += ov.x*ov.x + ov.y*ov.y + ov.z*ov.z + ov.w*ov.w;
        }
    }
}

// ---------------- partition (merged src + qf, fused qf stats) ----------------
__global__ void partition_kernel(const float* __restrict__ src, const float* __restrict__ qf,
                                 __half* __restrict__ memh, __half* __restrict__ tgth,
                                 float* __restrict__ tgt, float* __restrict__ p0) {
    __shared__ float red[16];
    int gb = blockIdx.x;
    bool isq = gb >= 32768;
    int g = (isq ? gb - 32768 : gb) * 256 + threadIdx.x;
    int idx = g * 2;
    int p = idx & 127, c = (idx >> 7) & 255, bw = idx >> 15;
    int b = bw >> 7, wblk = bw & 127;
    int h = (wblk >> 3) * 8 + (p >> 4), w = (wblk & 7) * 16 + (p & 15);
    const float* s = (isq ? qf : src) + (((size_t)b * 256 + c) * 128 + h) * 128 + w;
    float a0 = s[0], a1 = s[1];
    unsigned u = pack2h(a0, a1);
    if (isq) {
        *(unsigned*)(tgth + idx) = u;
        *(float2*)(tgt + idx) = make_float2(a0, a1);
        int tid = threadIdx.x, lane = tid & 31, wid = tid >> 5;
        float ss = a0 + a1, qq = a0*a0 + a1*a1;
#pragma unroll
        for (int off = 16; off; off >>= 1) {
            ss += __shfl_down_sync(0xffffffffu, ss, off);
            qq += __shfl_down_sync(0xffffffffu, qq, off);
        }
        if (lane == 0) { red[wid] = ss; red[8 + wid] = qq; }
        __syncthreads();
        if (tid == 0) {
            float ts = 0.f, tq = 0.f;
#pragma unroll
            for (int i = 0; i < 8; ++i) { ts += red[i]; tq += red[8 + i]; }
            int sb = gb - 32768;
            int win = sb >> 6, slot = sb & 63;
            p0[win*128 + slot*2] = ts; p0[win*128 + slot*2 + 1] = tq;
        }
    } else {
        *(unsigned*)(memh + idx) = u;
    }
}

// ---------------- all weights fp32 -> single fp16 (one launch) --------------
__global__ void conv_w_all(const float* __restrict__ qw, const float* __restrict__ kw,
                           const float* __restrict__ vw, const float* __restrict__ fc1w,
                           const float* __restrict__ fc2w, __half* __restrict__ hi) {
    int g = blockIdx.x * 256 + threadIdx.x;
    int l = g / 57344, r = g - l * 57344;
    const float* srcp;
    size_t oo;
    if (r < 8192)        { srcp = qw  + (size_t)l*65536  + (size_t)r*8;          oo = (size_t)l*458752 + (size_t)r*8; }
    else if (r < 16384)  { srcp = kw  + (size_t)l*65536  + (size_t)(r-8192)*8;   oo = (size_t)l*458752 + 65536  + (size_t)(r-8192)*8; }
    else if (r < 24576)  { srcp = vw  + (size_t)l*65536  + (size_t)(r-16384)*8;  oo = (size_t)l*458752 + 131072 + (size_t)(r-16384)*8; }
    else if (r < 40960)  { srcp = fc1w+ (size_t)l*131072 + (size_t)(r-24576)*8;  oo = (size_t)l*458752 + 196608 + (size_t)(r-24576)*8; }
    else                 { srcp = fc2w+ (size_t)l*131072 + (size_t)(r-40960)*8;  oo = (size_t)l*458752 + 327680 + (size_t)(r-40960)*8; }
    unsigned hh[4];
#pragma unroll
    for (int j = 0; j < 4; ++j) hh[j] = pack2h(srcp[2*j], srcp[2*j+1]);
    uint4 vh = {hh[0], hh[1], hh[2], hh[3]};
    *(uint4*)(hi + oo) = vh;
}

// ---------------- standalone GN+mix (partial-stats output) -------------------
__global__ __launch_bounds__(256)
void gn_mix_apply(const float* __restrict__ in, const float* __restrict__ basep,
                  const float* __restrict__ part, int pstride, int nparts,
                  const float* __restrict__ gw, const float* __restrict__ gb,
                  const float* __restrict__ ls, float* __restrict__ outf,
                  float* __restrict__ out_part) {
    __shared__ float red[16];
    int win = blockIdx.x, yb = blockIdx.y, tid = threadIdx.x, lane = tid & 31, wid = tid >> 5;
    float mean, rstd;
    read_stats(part, win, pstride, nparts, mean, rstd);
    float s2 = 0.f, q2 = 0.f;
    gn_mix_slice(win, yb, lane, wid, mean, rstd, in, basep, gw, gb, ls, outf, s2, q2, true);
#pragma unroll
    for (int off = 16; off; off >>= 1) {
        s2 += __shfl_down_sync(0xffffffffu, s2, off);
        q2 += __shfl_down_sync(0xffffffffu, q2, off);
    }
    if (lane == 0) { red[wid] = s2; red[8 + wid] = q2; }
    __syncthreads();
    if (tid == 0) {
        float ts = 0.f, tq = 0.f;
#pragma unroll
        for (int i = 0; i < 8; ++i) { ts += red[i]; tq += red[8 + i]; }
        out_part[win*16 + yb*2] = ts; out_part[win*16 + yb*2 + 1] = tq;
    }
}

// ---------------- final GN + fused window-reverse transpose ------------------
__global__ __launch_bounds__(256)
void gn_final_apply(const float* __restrict__ in, const float* __restrict__ part, int nparts,
                    const float* __restrict__ gw, const float* __restrict__ gb,
                    float* __restrict__ out) {
    __shared__ float tile[32 * 129];
    int win = blockIdx.x, yb = blockIdx.y, tid = threadIdx.x, lane = tid & 31, wid = tid >> 5;
    float mean, rstd;
    read_stats(part, win, 16, nparts, mean, rstd);
    size_t b0 = (size_t)win * WSZ + yb * 4096;
    const float4* src = (const float4*)(in + b0);
#pragma unroll
    for (int k = 0; k < 4; ++k) {
        int idx = tid + k * 256;
        int cl = idx >> 5, p4 = idx & 31;
        float w = gw[yb * 32 + cl], bb = gb[yb * 32 + cl];
        float4 v = src[idx];
        float* t = tile + cl * 129 + p4 * 4;
        t[0] = (v.x - mean) * rstd * w + bb;
        t[1] = (v.y - mean) * rstd * w + bb;
        t[2] = (v.z - mean) * rstd * w + bb;
        t[3] = (v.w - mean) * rstd * w + bb;
    }
    __syncthreads();
    int b = win >> 7, wblk = win & 127;
    int hb = (wblk >> 3) * 8, wb = (wblk & 7) * 16;
#pragma unroll
    for (int k = 0; k < 16; ++k) {
        int p = k * 8 + wid;
        int h = hb + (p >> 4), w = wb + (p & 15);
        int n = h * 128 + w;
        out[((size_t)n * 4 + b) * 256 + yb * 32 + lane] = tile[lane * 129 + p];
    }
}

// ---------------- tensor-core GEMM (cp.async double-buffered) ----------------
// mode 0: merged QKV + gn_mix1 slices (ob>=6)  mode 1: fc1+gn2  mode 2: fc2
__global__ __launch_bounds__(256, 2)
void gemm_tc_kernel(const __half* __restrict__ Wh,
                    const __half* __restrict__ Xa, const __half* __restrict__ Xb,
                    const float* __restrict__ Xf, const float* __restrict__ g2w,
                    const float* __restrict__ g2b, const float* __restrict__ statsp,
                    const float* __restrict__ b0p, const float* __restrict__ b1p,
                    const float* __restrict__ b2p,
                    float* __restrict__ Yf,
                    __half* __restrict__ Yq, __half* __restrict__ Yk, __half* __restrict__ Yv,
                    int CIN, int mode,
                    const float* __restrict__ base, const float* __restrict__ ls,
                    float* __restrict__ partials,
                    const float* __restrict__ mixIn, const float* __restrict__ mixBase,
                    const float* __restrict__ mixPart, int mixPstride, int mixNparts,
                    const float* __restrict__ mixGw, const float* __restrict__ mixGb,
                    const float* __restrict__ mixLs, float* __restrict__ mixOut) {
    extern __shared__ __half sb[];
    int win = blockIdx.x, ob = blockIdx.y;
    int tid = threadIdx.x, lane = tid & 31, wid = tid >> 5;

    if (mode == 0 && ob >= 6) {
        float mean, rstd, du0, du1;
        read_stats(mixPart, win, mixPstride, mixNparts, mean, rstd);
        gn_mix_slice(win, ob - 6, lane, wid, mean, rstd, mixIn, mixBase,
                     mixGw, mixGb, mixLs, mixOut, du0, du1, false);
        return;
    }

    __half* sWb[2] = { sb, sb + 17920 };
    __half* sXb[2] = { sb + 9216, sb + 17920 + 9216 };
    int wr = wid >> 1, wc = wid & 1;

    const __half* gW = Wh + (size_t)ob * 128 * CIN;
    const __half* X = nullptr;
    __half* outH = nullptr;
    const float* bias;
    int O, O0;
    float gmean = 0.f, grstd = 0.f;
    if (mode == 0) {
        int mat = ob >> 1;
        X = (mat == 0) ? Xa : Xb;
        bias = (mat == 0) ? b0p : (mat == 1 ? b1p : b2p);
        outH = (mat == 0) ? Yq : (mat == 1 ? Yk : Yv);
        O = 256; O0 = (ob & 1) * 128;
    } else if (mode == 1) {
        bias = b0p;
        O = 512; O0 = ob * 128;
        outH = Yq;
        read_stats(statsp, win, 16, 8, gmean, grstd);
    } else {
        X = Xa; bias = b0p;
        O = 256; O0 = ob * 128;
        outH = Yq;
    }
    const uint4* gX4 = (mode != 1) ? (const uint4*)X + (size_t)win * CIN * 16 : nullptr;
    const float* gXf = (mode == 1) ? Xf + (size_t)win * WSZ : nullptr;

    auto stage = [&](int t, int buf) {
        int kc = t << 6;
        __half* sW = sWb[buf];
        __half* sX = sXb[buf];
#pragma unroll
        for (int i = tid; i < 1024; i += 256) {
            int r = i >> 3, c4 = i & 7;
            CP_ASYNC16(smem_u32(sW + r * 72 + c4 * 8), gW + (size_t)r * CIN + kc + c4 * 8);
        }
        if (mode == 1) {
#pragma unroll
            for (int i = tid; i < 2048; i += 256) {
                int r = i >> 5, p4 = i & 31;
                int c = kc + r;
                float4 v = *(const float4*)(gXf + (size_t)c * 128 + p4 * 4);
                float w = g2w[c], bb = g2b[c];
                v.x = (v.x - gmean) * grstd * w + bb;
                v.y = (v.y - gmean) * grstd * w + bb;
                v.z = (v.z - gmean) * grstd * w + bb;
                v.w = (v.w - gmean) * grstd * w + bb;
                uint2 u = {pack2h(v.x, v.y), pack2h(v.z, v.w)};
                *(uint2*)(sX + r * 136 + p4 * 4) = u;
            }
        } else {
#pragma unroll
            for (int i = tid; i < 1024; i += 256) {
                int r = i >> 4, c4 = i & 15;
                CP_ASYNC16(smem_u32(sX + r * 136 + c4 * 8), gX4 + (kc + r) * 16 + c4);
            }
        }
        CP_COMMIT();
    };

    float acc[2][8][4];
#pragma unroll
    for (int mt = 0; mt < 2; ++mt)
#pragma unroll
        for (int nt = 0; nt < 8; ++nt)
#pragma unroll
            for (int e = 0; e < 4; ++e) acc[mt][nt][e] = 0.f;

    int aRow = (lane & 15), aCol = (lane >> 4) * 8;
    int brbase = ((lane >> 3) & 1) * 8 + (lane & 7);
    int bcofs  = (lane >> 4) * 8;
    int nkc = CIN >> 6;

    stage(0, 0);
    for (int t = 0; t < nkc; ++t) {
        CP_WAIT0();
        __syncthreads();
        if (t + 1 < nkc) stage(t + 1, (t + 1) & 1);
        const __half* sW = sWb[t & 1];
        const __half* sX = sXb[t & 1];
#pragma unroll
        for (int ks = 0; ks < 4; ++ks) {
            unsigned aW[2][4];
#pragma unroll
            for (int mt = 0; mt < 2; ++mt) {
                int ro = (wr * 32 + mt * 16 + aRow) * 72 + ks * 16 + aCol;
                LDSM_X4(aW[mt][0], aW[mt][1], aW[mt][2], aW[mt][3], smem_u32(sW + ro));
            }
#pragma unroll
            for (int np = 0; np < 4; ++np) {
                int bo = (ks * 16 + brbase) * 136 + wc * 64 + np * 16 + bcofs;
                unsigned bX[4];
                LDSM_X4_T(bX[0], bX[1], bX[2], bX[3], smem_u32(sX + bo));
#pragma unroll
                for (int mt = 0; mt < 2; ++mt) {
                    mma_f16(acc[mt][np*2],   aW[mt], bX);
                    mma_f16(acc[mt][np*2+1], aW[mt], bX + 2);
                }
            }
        }
    }

    float ssum = 0.f, ssq = 0.f;
#pragma unroll
    for (int mt = 0; mt < 2; ++mt)
#pragma unroll
        for (int nt = 0; nt < 8; ++nt) {
            int p = wc * 64 + nt * 8 + (lane & 3) * 2;
#pragma unroll
            for (int half = 0; half < 2; ++half) {
                int o = O0 + wr * 32 + mt * 16 + (lane >> 2) + half * 8;
                float bv = bias[o];
                float2 v;
                v.x = acc[mt][nt][half * 2]     + bv;
                v.y = acc[mt][nt][half * 2 + 1] + bv;
                size_t gi = ((size_t)win * O + o) * 128 + p;
                if (mode == 1) {
                    v.x = 0.5f * v.x * (1.f + erff(v.x * 0.70710678118654752f));
                    v.y = 0.5f * v.y * (1.f + erff(v.y * 0.70710678118654752f));
                } else if (mode == 2) {
                    float lsv = ls[o];
                    float2 b2 = *(const float2*)(base + gi);
                    v.x = b2.x + lsv * v.x;
                    v.y = b2.y + lsv * v.y;
                    *(float2*)(Yf + gi) = v;
                    ssum += v.x + v.y;
                    ssq  += v.x*v.x + v.y*v.y;
                }
                *(unsigned*)(outH + gi) = pack2h(v.x, v.y);
            }
        }

    if (mode == 2) {
        __syncthreads();
        float* red = (float*)sb;
#pragma unroll
        for (int off = 16; off; off >>= 1) {
            ssum += __shfl_down_sync(0xffffffffu, ssum, off);
            ssq  += __shfl_down_sync(0xffffffffu, ssq,  off);
        }
        if (lane == 0) { red[wid] = ssum; red[8 + wid] = ssq; }
        __syncthreads();
        if (tid == 0) {
            float ts = 0.f, tq = 0.f;
#pragma unroll
            for (int i = 0; i < 8; ++i) { ts += red[i]; tq += red[8 + i]; }
            partials[win*16 + ob*2] = ts; partials[win*16 + ob*2 + 1] = tq;
        }
    }
}

// ---------------- attention: 2 CTAs per window (64 rows each) ----------------
// grid (2, NW): blockIdx.x = half, blockIdx.y = win.
// warps: wr = wid>>1 (row tile of 16), wc = wid&1 (col half).
__global__ __launch_bounds__(256, 3)
void attn_kernel(const __half* __restrict__ Qh, const __half* __restrict__ Kh,
                 const __half* __restrict__ Vh,
                 const float* __restrict__ tgt2, float* __restrict__ tgt3,
                 float* __restrict__ p2) {
    extern __shared__ __half sat[];
    __half* sQb[2] = { sat, sat + 13824 };             // [64][72] each
    __half* sKb[2] = { sat + 4608, sat + 13824 + 4608 }; // [128][72] each
    __half* sP = sat;                                  // [64][136]  (after S)
    __half* sV = sat + 8704;                           // [128][136] (after S)
    __shared__ float sM[2][64], sS[2][64];
    __shared__ float ared[16];
    int half = blockIdx.x, win = blockIdx.y;
    int tid = threadIdx.x, lane = tid & 31, wid = tid >> 5;
    int wr = wid >> 1, wc = wid & 1;

    const uint4* gQ = (const uint4*)Qh + (size_t)win * 4096 + half * 2048;
    const uint4* gK = (const uint4*)Kh + (size_t)win * 4096;
    const uint4* gV = (const uint4*)Vh + (size_t)win * 4096;

    auto stage_s = [&](int ch, int buf) {
        __half* sQ = sQb[buf];
        __half* sK = sKb[buf];
#pragma unroll
        for (int i = tid; i < 512; i += 256) {
            int r = i >> 3, c4 = i & 7;
            CP_ASYNC16(smem_u32(sQ + r * 72 + c4 * 8), gQ + r * 32 + ch * 8 + c4);
        }
#pragma unroll
        for (int i = tid; i < 1024; i += 256) {
            int r = i >> 3, c4 = i & 7;
            CP_ASYNC16(smem_u32(sK + r * 72 + c4 * 8), gK + r * 32 + ch * 8 + c4);
        }
        CP_COMMIT();
    };
    auto stage_v = [&](int cv) {
#pragma unroll
        for (int i = tid; i < 2048; i += 256) {
            int r = i >> 4, c4 = i & 15;
            CP_ASYNC16(smem_u32(sV + r * 136 + c4 * 8), gV + r * 32 + cv * 16 + c4);
        }
        CP_COMMIT();
    };

    float acc[8][4];
#pragma unroll
    for (int j = 0; j < 8; ++j)
#pragma unroll
        for (int e = 0; e < 4; ++e) acc[j][e] = 0.f;

    int aRow = lane & 15, aCol = (lane >> 4) * 8;
    int kRow = (lane & 7) + ((lane >> 4) & 1) * 8;
    int kCol = ((lane >> 3) & 1) * 8;
    int tRow = ((lane >> 3) & 1) * 8 + (lane & 7);
    int tCol = (lane >> 4) * 8;

    // ---- S = Q(64 rows) @ K^T over 4 chunks of 64 channels ----
    stage_s(0, 0);
    for (int ch = 0; ch < 4; ++ch) {
        CP_WAIT0();
        __syncthreads();
        if (ch + 1 < 4) stage_s(ch + 1, (ch + 1) & 1);
        const __half* sQ = sQb[ch & 1];
        const __half* sK = sKb[ch & 1];
#pragma unroll
        for (int ks = 0; ks < 4; ++ks) {
            unsigned aQ[4];
            int ro = (wr * 16 + aRow) * 72 + ks * 16 + aCol;
            LDSM_X4(aQ[0], aQ[1], aQ[2], aQ[3], smem_u32(sQ + ro));
#pragma unroll
            for (int ngl = 0; ngl < 4; ++ngl) {
                int bo = ((wc * 4 + ngl) * 16 + kRow) * 72 + ks * 16 + kCol;
                unsigned bK[4];
                LDSM_X4(bK[0], bK[1], bK[2], bK[3], smem_u32(sK + bo));
                mma_f16(acc[ngl*2],   aQ, bK);
                mma_f16(acc[ngl*2+1], aQ, bK + 2);
            }
        }
    }

    // ---- softmax (cross-warp over wc) ----
    int rr = lane >> 2;
    float mx0 = -1e30f, mx1 = -1e30f;
#pragma unroll
    for (int j = 0; j < 8; ++j) {
        mx0 = fmaxf(mx0, fmaxf(acc[j][0], acc[j][1]));
        mx1 = fmaxf(mx1, fmaxf(acc[j][2], acc[j][3]));
    }
#pragma unroll
    for (int off = 1; off <= 2; off <<= 1) {
        mx0 = fmaxf(mx0, __shfl_xor_sync(0xffffffffu, mx0, off));
        mx1 = fmaxf(mx1, __shfl_xor_sync(0xffffffffu, mx1, off));
    }
    if ((lane & 3) == 0) {
        sM[wc][wr * 16 + rr] = mx0;
        sM[wc][wr * 16 + rr + 8] = mx1;
    }
    __syncthreads();                                  // (A) all S mma done
    stage_v(0);                                       // V cv0 load overlaps softmax
    mx0 = fmaxf(mx0, sM[wc ^ 1][wr * 16 + rr]);
    mx1 = fmaxf(mx1, sM[wc ^ 1][wr * 16 + rr + 8]);
    float s0 = 0.f, s1 = 0.f;
#pragma unroll
    for (int j = 0; j < 8; ++j) {
        acc[j][0] = expf(acc[j][0] - mx0); s0 += acc[j][0];
        acc[j][1] = expf(acc[j][1] - mx0); s0 += acc[j][1];
        acc[j][2] = expf(acc[j][2] - mx1); s1 += acc[j][2];
        acc[j][3] = expf(acc[j][3] - mx1); s1 += acc[j][3];
    }
#pragma unroll
    for (int off = 1; off <= 2; off <<= 1) {
        s0 += __shfl_xor_sync(0xffffffffu, s0, off);
        s1 += __shfl_xor_sync(0xffffffffu, s1, off);
    }
    if ((lane & 3) == 0) {
        sS[wc][wr * 16 + rr] = s0;
        sS[wc][wr * 16 + rr + 8] = s1;
    }
    __syncthreads();                                  // (B)
    float i0 = 1.f / (s0 + sS[wc ^ 1][wr * 16 + rr]);
    float i1 = 1.f / (s1 + sS[wc ^ 1][wr * 16 + rr + 8]);

    // ---- store P (fp16) into smem [64][136] ----
#pragma unroll
    for (int ngl = 0; ngl < 4; ++ngl)
#pragma unroll
        for (int h = 0; h < 2; ++h) {
            int j = ngl * 2 + h;
            int cb = wc * 64 + ngl * 16 + h * 8 + (lane & 3) * 2;
            int r0 = wr * 16 + rr;
            *(unsigned*)(sP + r0 * 136 + cb)       = pack2h(acc[j][0] * i0, acc[j][1] * i0);
            *(unsigned*)(sP + (r0 + 8) * 136 + cb) = pack2h(acc[j][2] * i1, acc[j][3] * i1);
        }
    CP_WAIT0();
    __syncthreads();                                  // (C) P + V cv0 ready

    // ---- O = P @ V over 2 cv chunks ----
    float ssum = 0.f, ssq = 0.f;
    for (int cv = 0; cv < 2; ++cv) {
        if (cv == 1) {
            __syncthreads();                          // (D) done reading sV cv0
            stage_v(1);
            CP_WAIT0();
            __syncthreads();                          // (E)
        }
        float oacc[8][4];
#pragma unroll
        for (int j = 0; j < 8; ++j)
#pragma unroll
            for (int e = 0; e < 4; ++e) oacc[j][e] = 0.f;
#pragma unroll
        for (int mk = 0; mk < 8; ++mk) {
            unsigned aP[4];
            int ro = (wr * 16 + aRow) * 136 + mk * 16 + aCol;
            LDSM_X4(aP[0], aP[1], aP[2], aP[3], smem_u32(sP + ro));
#pragma unroll
            for (int ngl = 0; ngl < 4; ++ngl) {
                int bo = (mk * 16 + tRow) * 136 + wc * 64 + ngl * 16 + tCol;
                unsigned vV[4];
                LDSM_X4_T(vV[0], vV[1], vV[2], vV[3], smem_u32(sV + bo));
                mma_f16(oacc[ngl*2],   aP, vV);
                mma_f16(oacc[ngl*2+1], aP, vV + 2);
            }
        }
#pragma unroll
        for (int j = 0; j < 8; ++j) {
            int col = cv * 128 + wc * 64 + j * 8 + (lane & 3) * 2;
            int n0 = half * 64 + wr * 16 + rr;
            size_t gi = (size_t)win * WSZ + n0 * 256 + col;
            float2 b0 = *(const float2*)(tgt2 + gi);
            float2 r0 = {b0.x + oacc[j][0], b0.y + oacc[j][1]};
            *(float2*)(tgt3 + gi) = r0;
            size_t gi1 = gi + 8 * 256;
            float2 b1 = *(const float2*)(tgt2 + gi1);
            float2 r1 = {b1.x + oacc[j][2], b1.y + oacc[j][3]};
            *(float2*)(tgt3 + gi1) = r1;
            ssum += r0.x + r0.y + r1.x + r1.y;
            ssq  += r0.x*r0.x + r0.y*r0.y + r1.x*r1.x + r1.y*r1.y;
        }
    }

    // ---- partial stats of this half -> p2 slot ----
#pragma unroll
    for (int off = 16; off; off >>= 1) {
        ssum += __shfl_down_sync(0xffffffffu, ssum, off);
        ssq  += __shfl_down_sync(0xffffffffu, ssq,  off);
    }
    if (lane == 0) { ared[wid] = ssum; ared[8 + wid] = ssq; }
    __syncthreads();
    if (tid == 0) {
        float ts = 0.f, tq = 0.f;
#pragma unroll
        for (int i = 0; i < 8; ++i) { ts += ared[i]; tq += ared[8 + i]; }
        p2[win*16 + half*2] = ts; p2[win*16 + half*2 + 1] = tq;
    }
}

// ---------------- host orchestration ---------------------------------------
extern "C" void kernel_launch(void* const* d_in, const int* in_sizes, int n_in,
                              void* d_out, int out_size) {
    const float* src  = (const float*)d_in[0];
    const float* qf   = (const float*)d_in[1];
    const float* gn1w = (const float*)d_in[2];
    const float* gn1b = (const float*)d_in[3];
    const float* gn2w = (const float*)d_in[4];
    const float* gn2b = (const float*)d_in[5];
    const float* ls1  = (const float*)d_in[6];
    const float* ls2  = (const float*)d_in[7];
    const float* ls3  = (const float*)d_in[8];
    const float* qw   = (const float*)d_in[9];
    const float* qb   = (const float*)d_in[10];
    const float* kw   = (const float*)d_in[11];
    const float* kb   = (const float*)d_in[12];
    const float* vw   = (const float*)d_in[13];
    const float* vb   = (const float*)d_in[14];
    const float* fc1w = (const float*)d_in[15];
    const float* fc1b = (const float*)d_in[16];
    const float* fc2w = (const float*)d_in[17];
    const float* fc2b = (const float*)d_in[18];
    const float* gnfw = (const float*)d_in[19];
    const float* gnfb = (const float*)d_in[20];
    float* out = (float*)d_out;

    float *tgt, *tgt2, *tgt3, *p0, *p1, *p2, *p3;
    __half *memh, *tgth, *qh, *kh, *vh, *hh, *wh;
    cudaGetSymbolAddress((void**)&tgt,  g_tgt);
    cudaGetSymbolAddress((void**)&tgt2, g_tgt2);
    cudaGetSymbolAddress((void**)&tgt3, g_tgt3);
    cudaGetSymbolAddress((void**)&p0,   g_p0);
    cudaGetSymbolAddress((void**)&p1,   g_p1);
    cudaGetSymbolAddress((void**)&p2,   g_p2);
    cudaGetSymbolAddress((void**)&p3,   g_p3);
    cudaGetSymbolAddress((void**)&memh, g_memh);
    cudaGetSymbolAddress((void**)&tgth, g_tgth);
    cudaGetSymbolAddress((void**)&qh,   g_qh);
    cudaGetSymbolAddress((void**)&kh,   g_kh);
    cudaGetSymbolAddress((void**)&vh,   g_vh);
    cudaGetSymbolAddress((void**)&hh,   g_hh);
    cudaGetSymbolAddress((void**)&wh,   g_wh);

    const int SM_ATTN = 55296;   // 2 x (sQ[64][72] + sK[128][72]) fp16
    const int SM_TC   = 71680;
    cudaFuncSetAttribute(attn_kernel,    cudaFuncAttributeMaxDynamicSharedMemorySize, SM_ATTN);
    cudaFuncSetAttribute(gemm_tc_kernel, cudaFuncAttributeMaxDynamicSharedMemorySize, SM_TC);

    partition_kernel<<<65536, 256>>>(src, qf, memh, tgth, tgt, p0);
    conv_w_all<<<448, 256>>>(qw, kw, vw, fc1w, fc2w, wh);

    for (int l = 0; l < 2; ++l) {
        int lC = l * CDIM;
        size_t lb = (size_t)l * 458752;
        const float* mp = (l == 0) ? p0 : p1;
        int mstride = (l == 0) ? 128 : 16;
        int mnp = (l == 0) ? 64 : 2;
        // merged: QKV gemm (ob<6) + gn_mix1 tgt->tgt2 (ob 6..13)
        gemm_tc_kernel<<<dim3(NW,14), 256, SM_TC>>>(wh + lb,
            tgth, memh, nullptr, nullptr, nullptr, nullptr,
            qb + lC, kb + lC, vb + lC,
            nullptr, qh, kh, vh, 256, 0, nullptr, nullptr, nullptr,
            tgt, tgt, mp, mstride, mnp, gn1w + lC, gn1b + lC, ls1 + lC, tgt2);
        // split attention: tgt3 = tgt2 + attn, partial stats -> p2 (2 slots)
        attn_kernel<<<dim3(2, NW), 256, SM_ATTN>>>(qh, kh, vh, tgt2, tgt3, p2);
        // tgt3 = tgt2 + ls2*mix(gn1(tgt3)); p3 <- 8-slot stats
        gn_mix_apply<<<dim3(NW,8), 256>>>(tgt3, tgt2, p2, 16, 2,
                                          gn1w + lC, gn1b + lC, ls2 + lC, tgt3, p3);
        // h = gelu(fc1(gn2(tgt3)))
        gemm_tc_kernel<<<dim3(NW,4), 256, SM_TC>>>(wh + lb + 196608,
            nullptr, nullptr, tgt3, gn2w + lC, gn2b + lC, p3,
            fc1b + (size_t)l*512, nullptr, nullptr,
            nullptr, hh, nullptr, nullptr, 256, 1, nullptr, nullptr, nullptr,
            nullptr, nullptr, nullptr, 0, 0, nullptr, nullptr, nullptr, nullptr);
        // tgt = tgt3 + ls3*fc2(h)  (+stats -> p1)
        gemm_tc_kernel<<<dim3(NW,2), 256, SM_TC>>>(wh + lb + 327680,
            hh, nullptr, nullptr, nullptr, nullptr, nullptr,
            fc2b + lC, nullptr, nullptr,
            tgt, tgth, nullptr, nullptr, 512, 2, tgt3, ls3 + lC, p1,
            nullptr, nullptr, nullptr, 0, 0, nullptr, nullptr, nullptr, nullptr);
    }

    gn_final_apply<<<dim3(NW,8), 256>>>(tgt, p1, 2, gnfw, gnfb, out);
}

// round 15
// speedup vs baseline: 1.0128x; 1.0128x over previous
#include <cuda_runtime.h>
#include <cuda_fp16.h>
#include <math.h>
#include <stdint.h>

#define NW   512
#define CDIM 256
#define PDIM 128
#define WSZ  (CDIM*PDIM)

// ---------------- scratch (static device globals; no allocations) ----------
__device__ float g_tgt [NW*WSZ];
__device__ float g_tgt2[NW*WSZ];
__device__ float g_tgt3[NW*WSZ];
__device__ __half g_memh[NW*WSZ];
__device__ __half g_tgth[NW*WSZ];
__device__ __half g_qh [NW*WSZ];
__device__ __half g_kh [NW*WSZ];
__device__ __half g_vh [NW*WSZ];
__device__ __half g_hh [NW*2*WSZ];
__device__ __half g_wh[2*458752];
__device__ float g_p0[NW*128];
__device__ float g_p1[NW*16];
__device__ float g_p3[NW*16];

// ================= helpers =================================================
__device__ __forceinline__ uint32_t smem_u32(const void* p) {
    uint32_t a;
    asm("{ .reg .u64 t; cvta.to.shared.u64 t, %1; cvt.u32.u64 %0, t; }" : "=r"(a) : "l"(p));
    return a;
}
#define LDSM_X4(r0,r1,r2,r3,addr) \
    asm volatile("ldmatrix.sync.aligned.m8n8.x4.shared.b16 {%0,%1,%2,%3}, [%4];" \
        : "=r"(r0),"=r"(r1),"=r"(r2),"=r"(r3) : "r"(addr))
#define LDSM_X4_T(r0,r1,r2,r3,addr) \
    asm volatile("ldmatrix.sync.aligned.m8n8.x4.trans.shared.b16 {%0,%1,%2,%3}, [%4];" \
        : "=r"(r0),"=r"(r1),"=r"(r2),"=r"(r3) : "r"(addr))
__device__ __forceinline__ void mma_f16(float* d, const unsigned* a, const unsigned* b) {
    asm volatile("mma.sync.aligned.m16n8k16.row.col.f32.f16.f16.f32 "
        "{%0,%1,%2,%3}, {%4,%5,%6,%7}, {%8,%9}, {%0,%1,%2,%3};"
        : "+f"(d[0]),"+f"(d[1]),"+f"(d[2]),"+f"(d[3])
        : "r"(a[0]),"r"(a[1]),"r"(a[2]),"r"(a[3]), "r"(b[0]),"r"(b[1]));
}
#define CP_ASYNC16(sa, gp) \
    asm volatile("cp.async.cg.shared.global [%0], [%1], 16;" :: "r"(sa), "l"(gp))
#define CP_COMMIT() asm volatile("cp.async.commit_group;" ::: "memory")
#define CP_WAIT0()  asm volatile("cp.async.wait_group 0;" ::: "memory")
__device__ __forceinline__ unsigned pack2h(float a, float b) {
    __half ah = __float2half_rn(a), bh = __float2half_rn(b);
    return (unsigned)__half_as_ushort(ah) | ((unsigned)__half_as_ushort(bh) << 16);
}
__device__ __forceinline__ void read_stats(const float* part, int win, int pstride, int nparts,
                                           float& mean, float& rstd) {
    float S = 0.f, Q = 0.f;
    for (int i = 0; i < nparts; ++i) { S += part[win*pstride + i*2]; Q += part[win*pstride + i*2 + 1]; }
    mean = S * (1.f / 32768.f);
    float var = Q * (1.f / 32768.f) - mean * mean;
    rstd = rsqrtf(var + 1e-5f);
}

// ---- shuffle-stencil GN+mix: one channel group (4 ch) per warp -------------
__device__ __forceinline__ void gn_mix_chans(
        int win, int cbase, int lane, float mean, float rstd,
        const float* __restrict__ in, const float* __restrict__ basep,
        const float* __restrict__ gw, const float* __restrict__ gb,
        const float* __restrict__ ls, float* __restrict__ outf,
        float& s2, float& q2, bool want_stats) {
    int p0 = lane * 4;
    int y = lane >> 2, x0 = (lane & 3) * 4;
    float vcnt = 3.f - (y == 0 ? 1.f : 0.f) - (y == 7 ? 1.f : 0.f);
    float rinv[4];
#pragma unroll
    for (int j = 0; j < 4; ++j) {
        int x = x0 + j;
        float hc = 3.f - (x == 0 ? 1.f : 0.f) - (x == 15 ? 1.f : 0.f);
        rinv[j] = 1.f / (hc * vcnt);
    }
#pragma unroll
    for (int ci = 0; ci < 4; ++ci) {
        int c = cbase + ci;
        size_t gi = (size_t)win * WSZ + c * 128 + p0;
        float w = gw[c], bb = gb[c];
        float4 v = *(const float4*)(in + gi);
        v.x = (v.x - mean) * rstd * w + bb;
        v.y = (v.y - mean) * rstd * w + bb;
        v.z = (v.z - mean) * rstd * w + bb;
        v.w = (v.w - mean) * rstd * w + bb;
        float L = __shfl_up_sync(0xffffffffu, v.w, 1);
        float R = __shfl_down_sync(0xffffffffu, v.x, 1);
        if (x0 == 0)  L = 0.f;
        if (x0 == 12) R = 0.f;
        float4 h;
        h.x = L + v.x + v.y;
        h.y = v.x + v.y + v.z;
        h.z = v.y + v.z + v.w;
        h.w = v.z + v.w + R;
        float4 up, dn;
        up.x = __shfl_up_sync(0xffffffffu, h.x, 4);
        up.y = __shfl_up_sync(0xffffffffu, h.y, 4);
        up.z = __shfl_up_sync(0xffffffffu, h.z, 4);
        up.w = __shfl_up_sync(0xffffffffu, h.w, 4);
        dn.x = __shfl_down_sync(0xffffffffu, h.x, 4);
        dn.y = __shfl_down_sync(0xffffffffu, h.y, 4);
        dn.z = __shfl_down_sync(0xffffffffu, h.z, 4);
        dn.w = __shfl_down_sync(0xffffffffu, h.w, 4);
        if (y == 0) { up.x = up.y = up.z = up.w = 0.f; }
        if (y == 7) { dn.x = dn.y = dn.z = dn.w = 0.f; }
        float o0 = (up.x + h.x + dn.x) * rinv[0] - v.x;
        float o1 = (up.y + h.y + dn.y) * rinv[1] - v.y;
        float o2 = (up.z + h.z + dn.z) * rinv[2] - v.z;
        float o3 = (up.w + h.w + dn.w) * rinv[3] - v.w;
        float4 bv = *(const float4*)(basep + gi);
        float lsv = ls[c];
        float4 ov = {bv.x + lsv * o0, bv.y + lsv * o1,
                     bv.z + lsv * o2, bv.w + lsv * o3};
        *(float4*)(outf + gi) = ov;
        if (want_stats) {
            s2 += ov.x + ov.y + ov.z + ov.w;
            q2 += ov.x*ov.x + ov.y*ov.y + ov.z*ov.z + ov.w*ov.w;
        }
    }
}

// ---------------- partition (merged src + qf, fused qf stats) ----------------
__global__ void partition_kernel(const float* __restrict__ src, const float* __restrict__ qf,
                                 __half* __restrict__ memh, __half* __restrict__ tgth,
                                 float* __restrict__ tgt, float* __restrict__ p0) {
    __shared__ float red[16];
    int gb = blockIdx.x;
    bool isq = gb >= 32768;
    int g = (isq ? gb - 32768 : gb) * 256 + threadIdx.x;
    int idx = g * 2;
    int p = idx & 127, c = (idx >> 7) & 255, bw = idx >> 15;
    int b = bw >> 7, wblk = bw & 127;
    int h = (wblk >> 3) * 8 + (p >> 4), w = (wblk & 7) * 16 + (p & 15);
    const float* s = (isq ? qf : src) + (((size_t)b * 256 + c) * 128 + h) * 128 + w;
    float a0 = s[0], a1 = s[1];
    unsigned u = pack2h(a0, a1);
    if (isq) {
        *(unsigned*)(tgth + idx) = u;
        *(float2*)(tgt + idx) = make_float2(a0, a1);
        int tid = threadIdx.x, lane = tid & 31, wid = tid >> 5;
        float ss = a0 + a1, qq = a0*a0 + a1*a1;
#pragma unroll
        for (int off = 16; off; off >>= 1) {
            ss += __shfl_down_sync(0xffffffffu, ss, off);
            qq += __shfl_down_sync(0xffffffffu, qq, off);
        }
        if (lane == 0) { red[wid] = ss; red[8 + wid] = qq; }
        __syncthreads();
        if (tid == 0) {
            float ts = 0.f, tq = 0.f;
#pragma unroll
            for (int i = 0; i < 8; ++i) { ts += red[i]; tq += red[8 + i]; }
            int sb = gb - 32768;
            int win = sb >> 6, slot = sb & 63;
            p0[win*128 + slot*2] = ts; p0[win*128 + slot*2 + 1] = tq;
        }
    } else {
        *(unsigned*)(memh + idx) = u;
    }
}

// ---------------- all weights fp32 -> single fp16 (one launch) --------------
__global__ void conv_w_all(const float* __restrict__ qw, const float* __restrict__ kw,
                           const float* __restrict__ vw, const float* __restrict__ fc1w,
                           const float* __restrict__ fc2w, __half* __restrict__ hi) {
    int g = blockIdx.x * 256 + threadIdx.x;
    int l = g / 57344, r = g - l * 57344;
    const float* srcp;
    size_t oo;
    if (r < 8192)        { srcp = qw  + (size_t)l*65536  + (size_t)r*8;          oo = (size_t)l*458752 + (size_t)r*8; }
    else if (r < 16384)  { srcp = kw  + (size_t)l*65536  + (size_t)(r-8192)*8;   oo = (size_t)l*458752 + 65536  + (size_t)(r-8192)*8; }
    else if (r < 24576)  { srcp = vw  + (size_t)l*65536  + (size_t)(r-16384)*8;  oo = (size_t)l*458752 + 131072 + (size_t)(r-16384)*8; }
    else if (r < 40960)  { srcp = fc1w+ (size_t)l*131072 + (size_t)(r-24576)*8;  oo = (size_t)l*458752 + 196608 + (size_t)(r-24576)*8; }
    else                 { srcp = fc2w+ (size_t)l*131072 + (size_t)(r-40960)*8;  oo = (size_t)l*458752 + 327680 + (size_t)(r-40960)*8; }
    unsigned hh[4];
#pragma unroll
    for (int j = 0; j < 4; ++j) hh[j] = pack2h(srcp[2*j], srcp[2*j+1]);
    uint4 vh = {hh[0], hh[1], hh[2], hh[3]};
    *(uint4*)(hi + oo) = vh;
}

// ---------------- final GN + fused window-reverse transpose ------------------
__global__ __launch_bounds__(256)
void gn_final_apply(const float* __restrict__ in, const float* __restrict__ part, int nparts,
                    const float* __restrict__ gw, const float* __restrict__ gb,
                    float* __restrict__ out) {
    __shared__ float tile[32 * 129];
    int win = blockIdx.x, yb = blockIdx.y, tid = threadIdx.x, lane = tid & 31, wid = tid >> 5;
    float mean, rstd;
    read_stats(part, win, 16, nparts, mean, rstd);
    size_t b0 = (size_t)win * WSZ + yb * 4096;
    const float4* src = (const float4*)(in + b0);
#pragma unroll
    for (int k = 0; k < 4; ++k) {
        int idx = tid + k * 256;
        int cl = idx >> 5, p4 = idx & 31;
        float w = gw[yb * 32 + cl], bb = gb[yb * 32 + cl];
        float4 v = src[idx];
        float* t = tile + cl * 129 + p4 * 4;
        t[0] = (v.x - mean) * rstd * w + bb;
        t[1] = (v.y - mean) * rstd * w + bb;
        t[2] = (v.z - mean) * rstd * w + bb;
        t[3] = (v.w - mean) * rstd * w + bb;
    }
    __syncthreads();
    int b = win >> 7, wblk = win & 127;
    int hb = (wblk >> 3) * 8, wb = (wblk & 7) * 16;
#pragma unroll
    for (int k = 0; k < 16; ++k) {
        int p = k * 8 + wid;
        int h = hb + (p >> 4), w = wb + (p & 15);
        int n = h * 128 + w;
        out[((size_t)n * 4 + b) * 256 + yb * 32 + lane] = tile[lane * 129 + p];
    }
}

// ---------------- tensor-core GEMM (cp.async double-buffered) ----------------
// mode 0: merged QKV + gn_mix1 slices (ob>=6)  mode 1: fc1+gn2  mode 2: fc2
__global__ __launch_bounds__(256, 2)
void gemm_tc_kernel(const __half* __restrict__ Wh,
                    const __half* __restrict__ Xa, const __half* __restrict__ Xb,
                    const float* __restrict__ Xf, const float* __restrict__ g2w,
                    const float* __restrict__ g2b, const float* __restrict__ statsp,
                    const float* __restrict__ b0p, const float* __restrict__ b1p,
                    const float* __restrict__ b2p,
                    float* __restrict__ Yf,
                    __half* __restrict__ Yq, __half* __restrict__ Yk, __half* __restrict__ Yv,
                    int CIN, int mode,
                    const float* __restrict__ base, const float* __restrict__ ls,
                    float* __restrict__ partials,
                    const float* __restrict__ mixIn, const float* __restrict__ mixBase,
                    const float* __restrict__ mixPart, int mixPstride, int mixNparts,
                    const float* __restrict__ mixGw, const float* __restrict__ mixGb,
                    const float* __restrict__ mixLs, float* __restrict__ mixOut) {
    extern __shared__ __half sb[];
    int win = blockIdx.x, ob = blockIdx.y;
    int tid = threadIdx.x, lane = tid & 31, wid = tid >> 5;

    if (mode == 0 && ob >= 6) {
        float mean, rstd, du0 = 0.f, du1 = 0.f;
        read_stats(mixPart, win, mixPstride, mixNparts, mean, rstd);
        gn_mix_chans(win, (ob - 6) * 32 + wid * 4, lane, mean, rstd, mixIn, mixBase,
                     mixGw, mixGb, mixLs, mixOut, du0, du1, false);
        return;
    }

    __half* sWb[2] = { sb, sb + 17920 };
    __half* sXb[2] = { sb + 9216, sb + 17920 + 9216 };
    int wr = wid >> 1, wc = wid & 1;

    const __half* gW = Wh + (size_t)ob * 128 * CIN;
    const __half* X = nullptr;
    __half* outH = nullptr;
    const float* bias;
    int O, O0;
    float gmean = 0.f, grstd = 0.f;
    if (mode == 0) {
        int mat = ob >> 1;
        X = (mat == 0) ? Xa : Xb;
        bias = (mat == 0) ? b0p : (mat == 1 ? b1p : b2p);
        outH = (mat == 0) ? Yq : (mat == 1 ? Yk : Yv);
        O = 256; O0 = (ob & 1) * 128;
    } else if (mode == 1) {
        bias = b0p;
        O = 512; O0 = ob * 128;
        outH = Yq;
        read_stats(statsp, win, 16, 1, gmean, grstd);
    } else {
        X = Xa; bias = b0p;
        O = 256; O0 = ob * 128;
        outH = Yq;
    }
    const uint4* gX4 = (mode != 1) ? (const uint4*)X + (size_t)win * CIN * 16 : nullptr;
    const float* gXf = (mode == 1) ? Xf + (size_t)win * WSZ : nullptr;

    auto stage = [&](int t, int buf) {
        int kc = t << 6;
        __half* sW = sWb[buf];
        __half* sX = sXb[buf];
#pragma unroll
        for (int i = tid; i < 1024; i += 256) {
            int r = i >> 3, c4 = i & 7;
            CP_ASYNC16(smem_u32(sW + r * 72 + c4 * 8), gW + (size_t)r * CIN + kc + c4 * 8);
        }
        if (mode == 1) {
#pragma unroll
            for (int i = tid; i < 2048; i += 256) {
                int r = i >> 5, p4 = i & 31;
                int c = kc + r;
                float4 v = *(const float4*)(gXf + (size_t)c * 128 + p4 * 4);
                float w = g2w[c], bb = g2b[c];
                v.x = (v.x - gmean) * grstd * w + bb;
                v.y = (v.y - gmean) * grstd * w + bb;
                v.z = (v.z - gmean) * grstd * w + bb;
                v.w = (v.w - gmean) * grstd * w + bb;
                uint2 u = {pack2h(v.x, v.y), pack2h(v.z, v.w)};
                *(uint2*)(sX + r * 136 + p4 * 4) = u;
            }
        } else {
#pragma unroll
            for (int i = tid; i < 1024; i += 256) {
                int r = i >> 4, c4 = i & 15;
                CP_ASYNC16(smem_u32(sX + r * 136 + c4 * 8), gX4 + (kc + r) * 16 + c4);
            }
        }
        CP_COMMIT();
    };

    float acc[2][8][4];
#pragma unroll
    for (int mt = 0; mt < 2; ++mt)
#pragma unroll
        for (int nt = 0; nt < 8; ++nt)
#pragma unroll
            for (int e = 0; e < 4; ++e) acc[mt][nt][e] = 0.f;

    int aRow = (lane & 15), aCol = (lane >> 4) * 8;
    int brbase = ((lane >> 3) & 1) * 8 + (lane & 7);
    int bcofs  = (lane >> 4) * 8;
    int nkc = CIN >> 6;

    stage(0, 0);
    for (int t = 0; t < nkc; ++t) {
        CP_WAIT0();
        __syncthreads();
        if (t + 1 < nkc) stage(t + 1, (t + 1) & 1);
        const __half* sW = sWb[t & 1];
        const __half* sX = sXb[t & 1];
#pragma unroll
        for (int ks = 0; ks < 4; ++ks) {
            unsigned aW[2][4];
#pragma unroll
            for (int mt = 0; mt < 2; ++mt) {
                int ro = (wr * 32 + mt * 16 + aRow) * 72 + ks * 16 + aCol;
                LDSM_X4(aW[mt][0], aW[mt][1], aW[mt][2], aW[mt][3], smem_u32(sW + ro));
            }
#pragma unroll
            for (int np = 0; np < 4; ++np) {
                int bo = (ks * 16 + brbase) * 136 + wc * 64 + np * 16 + bcofs;
                unsigned bX[4];
                LDSM_X4_T(bX[0], bX[1], bX[2], bX[3], smem_u32(sX + bo));
#pragma unroll
                for (int mt = 0; mt < 2; ++mt) {
                    mma_f16(acc[mt][np*2],   aW[mt], bX);
                    mma_f16(acc[mt][np*2+1], aW[mt], bX + 2);
                }
            }
        }
    }

    float ssum = 0.f, ssq = 0.f;
#pragma unroll
    for (int mt = 0; mt < 2; ++mt)
#pragma unroll
        for (int nt = 0; nt < 8; ++nt) {
            int p = wc * 64 + nt * 8 + (lane & 3) * 2;
#pragma unroll
            for (int half = 0; half < 2; ++half) {
                int o = O0 + wr * 32 + mt * 16 + (lane >> 2) + half * 8;
                float bv = bias[o];
                float2 v;
                v.x = acc[mt][nt][half * 2]     + bv;
                v.y = acc[mt][nt][half * 2 + 1] + bv;
                size_t gi = ((size_t)win * O + o) * 128 + p;
                if (mode == 1) {
                    v.x = 0.5f * v.x * (1.f + erff(v.x * 0.70710678118654752f));
                    v.y = 0.5f * v.y * (1.f + erff(v.y * 0.70710678118654752f));
                } else if (mode == 2) {
                    float lsv = ls[o];
                    float2 b2 = *(const float2*)(base + gi);
                    v.x = b2.x + lsv * v.x;
                    v.y = b2.y + lsv * v.y;
                    *(float2*)(Yf + gi) = v;
                    ssum += v.x + v.y;
                    ssq  += v.x*v.x + v.y*v.y;
                }
                *(unsigned*)(outH + gi) = pack2h(v.x, v.y);
            }
        }

    if (mode == 2) {
        __syncthreads();
        float* red = (float*)sb;
#pragma unroll
        for (int off = 16; off; off >>= 1) {
            ssum += __shfl_down_sync(0xffffffffu, ssum, off);
            ssq  += __shfl_down_sync(0xffffffffu, ssq,  off);
        }
        if (lane == 0) { red[wid] = ssum; red[8 + wid] = ssq; }
        __syncthreads();
        if (tid == 0) {
            float ts = 0.f, tq = 0.f;
#pragma unroll
            for (int i = 0; i < 8; ++i) { ts += red[i]; tq += red[8 + i]; }
            partials[win*16 + ob*2] = ts; partials[win*16 + ob*2 + 1] = tq;
        }
    }
}

// ---------------- attention (512 threads, fused gn_mix2) ---------------------
// one CTA per window; 16 warps = 8 row-tiles x 2 col-halves.
__global__ __launch_bounds__(512, 1)
void attn_kernel(const __half* __restrict__ Qh, const __half* __restrict__ Kh,
                 const __half* __restrict__ Vh,
                 const float* __restrict__ tgt2, float* __restrict__ tgt3,
                 const float* __restrict__ g1w, const float* __restrict__ g1b,
                 const float* __restrict__ ls2, float* __restrict__ p3) {
    extern __shared__ __half sat[];
    __half* sQb[2] = { sat, sat + 18432 };
    __half* sKb[2] = { sat + 9216, sat + 18432 + 9216 };
    __half* sP = sat;                                  // [128][136]
    __half* sV = sat + 17408;                          // [128][136]
    __shared__ float sM[2][128], sSm[2][128];
    __shared__ float ared[32];
    __shared__ float stats2[2];
    int win = blockIdx.x;
    int tid = threadIdx.x, lane = tid & 31, wid = tid >> 5;
    int wr = wid >> 1, wc = wid & 1;

    const uint4* gQ = (const uint4*)Qh + (size_t)win * 4096;
    const uint4* gK = (const uint4*)Kh + (size_t)win * 4096;
    const uint4* gV = (const uint4*)Vh + (size_t)win * 4096;

    auto stage_s = [&](int ch, int buf) {
        __half* sQ = sQb[buf];
        __half* sK = sKb[buf];
#pragma unroll
        for (int i = tid; i < 1024; i += 512) {
            int r = i >> 3, c4 = i & 7;
            int gi = r * 32 + ch * 8 + c4;
            int so = r * 72 + c4 * 8;
            CP_ASYNC16(smem_u32(sQ + so), gQ + gi);
            CP_ASYNC16(smem_u32(sK + so), gK + gi);
        }
        CP_COMMIT();
    };
    auto stage_v = [&](int cv) {
#pragma unroll
        for (int i = tid; i < 2048; i += 512) {
            int r = i >> 4, c4 = i & 15;
            CP_ASYNC16(smem_u32(sV + r * 136 + c4 * 8), gV + r * 32 + cv * 16 + c4);
        }
        CP_COMMIT();
    };

    float acc[8][4];
#pragma unroll
    for (int j = 0; j < 8; ++j)
#pragma unroll
        for (int e = 0; e < 4; ++e) acc[j][e] = 0.f;

    int aRow = lane & 15, aCol = (lane >> 4) * 8;
    int kRow = (lane & 7) + ((lane >> 4) & 1) * 8;
    int kCol = ((lane >> 3) & 1) * 8;
    int tRow = ((lane >> 3) & 1) * 8 + (lane & 7);
    int tCol = (lane >> 4) * 8;
    int rr = lane >> 2;

    // ---- S = Q @ K^T over 4 chunks of 64 channels ----
    stage_s(0, 0);
    for (int ch = 0; ch < 4; ++ch) {
        CP_WAIT0();
        __syncthreads();
        if (ch + 1 < 4) stage_s(ch + 1, (ch + 1) & 1);
        const __half* sQ = sQb[ch & 1];
        const __half* sK = sKb[ch & 1];
#pragma unroll
        for (int ks = 0; ks < 4; ++ks) {
            unsigned aQ[4];
            int ro = (wr * 16 + aRow) * 72 + ks * 16 + aCol;
            LDSM_X4(aQ[0], aQ[1], aQ[2], aQ[3], smem_u32(sQ + ro));
#pragma unroll
            for (int ngl = 0; ngl < 4; ++ngl) {
                int bo = ((wc * 4 + ngl) * 16 + kRow) * 72 + ks * 16 + kCol;
                unsigned bK[4];
                LDSM_X4(bK[0], bK[1], bK[2], bK[3], smem_u32(sK + bo));
                mma_f16(acc[ngl*2],   aQ, bK);
                mma_f16(acc[ngl*2+1], aQ, bK + 2);
            }
        }
    }

    // ---- softmax (cross-warp over the two col-halves) ----
    float mx0 = -1e30f, mx1 = -1e30f;
#pragma unroll
    for (int j = 0; j < 8; ++j) {
        mx0 = fmaxf(mx0, fmaxf(acc[j][0], acc[j][1]));
        mx1 = fmaxf(mx1, fmaxf(acc[j][2], acc[j][3]));
    }
#pragma unroll
    for (int off = 1; off <= 2; off <<= 1) {
        mx0 = fmaxf(mx0, __shfl_xor_sync(0xffffffffu, mx0, off));
        mx1 = fmaxf(mx1, __shfl_xor_sync(0xffffffffu, mx1, off));
    }
    if ((lane & 3) == 0) {
        sM[wc][wr * 16 + rr] = mx0;
        sM[wc][wr * 16 + rr + 8] = mx1;
    }
    __syncthreads();                                  // (A) all S mma done
    stage_v(0);                                       // overlap V cv0 with softmax
    mx0 = fmaxf(mx0, sM[wc ^ 1][wr * 16 + rr]);
    mx1 = fmaxf(mx1, sM[wc ^ 1][wr * 16 + rr + 8]);
    float s0 = 0.f, s1 = 0.f;
#pragma unroll
    for (int j = 0; j < 8; ++j) {
        acc[j][0] = expf(acc[j][0] - mx0); s0 += acc[j][0];
        acc[j][1] = expf(acc[j][1] - mx0); s0 += acc[j][1];
        acc[j][2] = expf(acc[j][2] - mx1); s1 += acc[j][2];
        acc[j][3] = expf(acc[j][3] - mx1); s1 += acc[j][3];
    }
#pragma unroll
    for (int off = 1; off <= 2; off <<= 1) {
        s0 += __shfl_xor_sync(0xffffffffu, s0, off);
        s1 += __shfl_xor_sync(0xffffffffu, s1, off);
    }
    if ((lane & 3) == 0) {
        sSm[wc][wr * 16 + rr] = s0;
        sSm[wc][wr * 16 + rr + 8] = s1;
    }
    __syncthreads();                                  // (B)
    float i0 = 1.f / (s0 + sSm[wc ^ 1][wr * 16 + rr]);
    float i1 = 1.f / (s1 + sSm[wc ^ 1][wr * 16 + rr + 8]);

    // ---- store P (fp16) into smem [128][136] ----
#pragma unroll
    for (int ngl = 0; ngl < 4; ++ngl)
#pragma unroll
        for (int h = 0; h < 2; ++h) {
            int j = ngl * 2 + h;
            int cb = wc * 64 + ngl * 16 + h * 8 + (lane & 3) * 2;
            int r0 = wr * 16 + rr;
            *(unsigned*)(sP + r0 * 136 + cb)       = pack2h(acc[j][0] * i0, acc[j][1] * i0);
            *(unsigned*)(sP + (r0 + 8) * 136 + cb) = pack2h(acc[j][2] * i1, acc[j][3] * i1);
        }
    CP_WAIT0();
    __syncthreads();                                  // (C) P + V cv0 ready

    // ---- O = P @ V over 2 cv chunks ----
    float ssum = 0.f, ssq = 0.f;
    for (int cv = 0; cv < 2; ++cv) {
        if (cv == 1) {
            __syncthreads();                          // (D)
            stage_v(1);
            CP_WAIT0();
            __syncthreads();                          // (E)
        }
        float oacc[8][4];
#pragma unroll
        for (int j = 0; j < 8; ++j)
#pragma unroll
            for (int e = 0; e < 4; ++e) oacc[j][e] = 0.f;
#pragma unroll
        for (int mk = 0; mk < 8; ++mk) {
            unsigned aP[4];
            int ro = (wr * 16 + aRow) * 136 + mk * 16 + aCol;
            LDSM_X4(aP[0], aP[1], aP[2], aP[3], smem_u32(sP + ro));
#pragma unroll
            for (int ngl = 0; ngl < 4; ++ngl) {
                int bo = (mk * 16 + tRow) * 136 + wc * 64 + ngl * 16 + tCol;
                unsigned vV[4];
                LDSM_X4_T(vV[0], vV[1], vV[2], vV[3], smem_u32(sV + bo));
                mma_f16(oacc[ngl*2],   aP, vV);
                mma_f16(oacc[ngl*2+1], aP, vV + 2);
            }
        }
#pragma unroll
        for (int j = 0; j < 8; ++j) {
            int col = cv * 128 + wc * 64 + j * 8 + (lane & 3) * 2;
            int n0 = wr * 16 + rr;
            size_t gi = (size_t)win * WSZ + n0 * 256 + col;
            float2 b0 = *(const float2*)(tgt2 + gi);
            float2 r0 = {b0.x + oacc[j][0], b0.y + oacc[j][1]};
            *(float2*)(tgt3 + gi) = r0;
            size_t gi1 = gi + 8 * 256;
            float2 b1 = *(const float2*)(tgt2 + gi1);
            float2 r1 = {b1.x + oacc[j][2], b1.y + oacc[j][3]};
            *(float2*)(tgt3 + gi1) = r1;
            ssum += r0.x + r0.y + r1.x + r1.y;
            ssq  += r0.x*r0.x + r0.y*r0.y + r1.x*r1.x + r1.y*r1.y;
        }
    }

    // ---- stats of attn tgt3 (for gn1 in mix2) ----
#pragma unroll
    for (int off = 16; off; off >>= 1) {
        ssum += __shfl_down_sync(0xffffffffu, ssum, off);
        ssq  += __shfl_down_sync(0xffffffffu, ssq,  off);
    }
    if (lane == 0) { ared[wid] = ssum; ared[16 + wid] = ssq; }
    __syncthreads();
    if (tid == 0) {
        float ts = 0.f, tq = 0.f;
#pragma unroll
        for (int i = 0; i < 16; ++i) { ts += ared[i]; tq += ared[16 + i]; }
        float mean = ts * (1.f / 32768.f);
        float var  = tq * (1.f / 32768.f) - mean * mean;
        stats2[0] = mean; stats2[1] = rsqrtf(var + 1e-5f);
    }
    __syncthreads();
    float mean2 = stats2[0], rstd2 = stats2[1];

    // ---- fused mix2 across 16 warps (64 channels per yb pass) ----
    float s3 = 0.f, q3 = 0.f;
    for (int yb = 0; yb < 4; ++yb)
        gn_mix_chans(win, yb * 64 + wid * 4, lane, mean2, rstd2, tgt3, tgt2,
                     g1w, g1b, ls2, tgt3, s3, q3, true);
#pragma unroll
    for (int off = 16; off; off >>= 1) {
        s3 += __shfl_down_sync(0xffffffffu, s3, off);
        q3 += __shfl_down_sync(0xffffffffu, q3, off);
    }
    if (lane == 0) { ared[wid] = s3; ared[16 + wid] = q3; }
    __syncthreads();
    if (tid == 0) {
        float ts = 0.f, tq = 0.f;
#pragma unroll
        for (int i = 0; i < 16; ++i) { ts += ared[i]; tq += ared[16 + i]; }
        p3[win*16 + 0] = ts; p3[win*16 + 1] = tq;
    }
}

// ---------------- host orchestration ---------------------------------------
extern "C" void kernel_launch(void* const* d_in, const int* in_sizes, int n_in,
                              void* d_out, int out_size) {
    const float* src  = (const float*)d_in[0];
    const float* qf   = (const float*)d_in[1];
    const float* gn1w = (const float*)d_in[2];
    const float* gn1b = (const float*)d_in[3];
    const float* gn2w = (const float*)d_in[4];
    const float* gn2b = (const float*)d_in[5];
    const float* ls1  = (const float*)d_in[6];
    const float* ls2  = (const float*)d_in[7];
    const float* ls3  = (const float*)d_in[8];
    const float* qw   = (const float*)d_in[9];
    const float* qb   = (const float*)d_in[10];
    const float* kw   = (const float*)d_in[11];
    const float* kb   = (const float*)d_in[12];
    const float* vw   = (const float*)d_in[13];
    const float* vb   = (const float*)d_in[14];
    const float* fc1w = (const float*)d_in[15];
    const float* fc1b = (const float*)d_in[16];
    const float* fc2w = (const float*)d_in[17];
    const float* fc2b = (const float*)d_in[18];
    const float* gnfw = (const float*)d_in[19];
    const float* gnfb = (const float*)d_in[20];
    float* out = (float*)d_out;

    float *tgt, *tgt2, *tgt3, *p0, *p1, *p3;
    __half *memh, *tgth, *qh, *kh, *vh, *hh, *wh;
    cudaGetSymbolAddress((void**)&tgt,  g_tgt);
    cudaGetSymbolAddress((void**)&tgt2, g_tgt2);
    cudaGetSymbolAddress((void**)&tgt3, g_tgt3);
    cudaGetSymbolAddress((void**)&p0,   g_p0);
    cudaGetSymbolAddress((void**)&p1,   g_p1);
    cudaGetSymbolAddress((void**)&p3,   g_p3);
    cudaGetSymbolAddress((void**)&memh, g_memh);
    cudaGetSymbolAddress((void**)&tgth, g_tgth);
    cudaGetSymbolAddress((void**)&qh,   g_qh);
    cudaGetSymbolAddress((void**)&kh,   g_kh);
    cudaGetSymbolAddress((void**)&vh,   g_vh);
    cudaGetSymbolAddress((void**)&hh,   g_hh);
    cudaGetSymbolAddress((void**)&wh,   g_wh);

    const int SM_ATTN = 73728;
    const int SM_TC   = 71680;
    cudaFuncSetAttribute(attn_kernel,    cudaFuncAttributeMaxDynamicSharedMemorySize, SM_ATTN);
    cudaFuncSetAttribute(gemm_tc_kernel, cudaFuncAttributeMaxDynamicSharedMemorySize, SM_TC);

    partition_kernel<<<65536, 256>>>(src, qf, memh, tgth, tgt, p0);
    conv_w_all<<<448, 256>>>(qw, kw, vw, fc1w, fc2w, wh);

    for (int l = 0; l < 2; ++l) {
        int lC = l * CDIM;
        size_t lb = (size_t)l * 458752;
        const float* mp = (l == 0) ? p0 : p1;
        int mstride = (l == 0) ? 128 : 16;
        int mnp = (l == 0) ? 64 : 2;
        // merged: QKV gemm (ob<6) + gn_mix1 tgt->tgt2 (ob 6..13)
        gemm_tc_kernel<<<dim3(NW,14), 256, SM_TC>>>(wh + lb,
            tgth, memh, nullptr, nullptr, nullptr, nullptr,
            qb + lC, kb + lC, vb + lC,
            nullptr, qh, kh, vh, 256, 0, nullptr, nullptr, nullptr,
            tgt, tgt, mp, mstride, mnp, gn1w + lC, gn1b + lC, ls1 + lC, tgt2);
        // attn + fused mix2 (512 threads): tgt3 final, p3 stats for gn2
        attn_kernel<<<NW, 512, SM_ATTN>>>(qh, kh, vh, tgt2, tgt3,
                                          gn1w + lC, gn1b + lC, ls2 + lC, p3);
        // h = gelu(fc1(gn2(tgt3)))
        gemm_tc_kernel<<<dim3(NW,4), 256, SM_TC>>>(wh + lb + 196608,
            nullptr, nullptr, tgt3, gn2w + lC, gn2b + lC, p3,
            fc1b + (size_t)l*512, nullptr, nullptr,
            nullptr, hh, nullptr, nullptr, 256, 1, nullptr, nullptr, nullptr,
            nullptr, nullptr, nullptr, 0, 0, nullptr, nullptr, nullptr, nullptr);
        // tgt = tgt3 + ls3*fc2(h)  (+stats -> p1)
        gemm_tc_kernel<<<dim3(NW,2), 256, SM_TC>>>(wh + lb + 327680,
            hh, nullptr, nullptr, nullptr, nullptr, nullptr,
            fc2b + lC, nullptr, nullptr,
            tgt, tgth, nullptr, nullptr, 512, 2, tgt3, ls3 + lC, p1,
            nullptr, nullptr, nullptr, 0, 0, nullptr, nullptr, nullptr, nullptr);
    }

    gn_final_apply<<<dim3(NW,8), 256>>>(tgt, p1, 2, gnfw, gnfb, out);
}

// round 16
// speedup vs baseline: 1.0629x; 1.0495x over previous
#include <cuda_runtime.h>
#include <cuda_fp16.h>
#include <math.h>
#include <stdint.h>

#define NW   512
#define CDIM 256
#define PDIM 128
#define WSZ  (CDIM*PDIM)

// ---------------- scratch (static device globals; no allocations) ----------
__device__ float g_tgt [NW*WSZ];
__device__ float g_tgt2[NW*WSZ];
__device__ float g_tgt3[NW*WSZ];
__device__ __half g_memh[NW*WSZ];
__device__ __half g_tgth[NW*WSZ];
__device__ __half g_qh [NW*WSZ];
__device__ __half g_kh [NW*WSZ];
__device__ __half g_vh [NW*WSZ];
__device__ __half g_hinh[NW*WSZ];
__device__ __half g_hh [NW*2*WSZ];
__device__ __half g_wh[2*458752];
__device__ float g_p0[NW*128];
__device__ float g_p1[NW*16];

// ================= helpers =================================================
__device__ __forceinline__ uint32_t smem_u32(const void* p) {
    uint32_t a;
    asm("{ .reg .u64 t; cvta.to.shared.u64 t, %1; cvt.u32.u64 %0, t; }" : "=r"(a) : "l"(p));
    return a;
}
#define LDSM_X4(r0,r1,r2,r3,addr) \
    asm volatile("ldmatrix.sync.aligned.m8n8.x4.shared.b16 {%0,%1,%2,%3}, [%4];" \
        : "=r"(r0),"=r"(r1),"=r"(r2),"=r"(r3) : "r"(addr))
#define LDSM_X4_T(r0,r1,r2,r3,addr) \
    asm volatile("ldmatrix.sync.aligned.m8n8.x4.trans.shared.b16 {%0,%1,%2,%3}, [%4];" \
        : "=r"(r0),"=r"(r1),"=r"(r2),"=r"(r3) : "r"(addr))
__device__ __forceinline__ void mma_f16(float* d, const unsigned* a, const unsigned* b) {
    asm volatile("mma.sync.aligned.m16n8k16.row.col.f32.f16.f16.f32 "
        "{%0,%1,%2,%3}, {%4,%5,%6,%7}, {%8,%9}, {%0,%1,%2,%3};"
        : "+f"(d[0]),"+f"(d[1]),"+f"(d[2]),"+f"(d[3])
        : "r"(a[0]),"r"(a[1]),"r"(a[2]),"r"(a[3]), "r"(b[0]),"r"(b[1]));
}
#define CP_ASYNC16(sa, gp) \
    asm volatile("cp.async.cg.shared.global [%0], [%1], 16;" :: "r"(sa), "l"(gp))
#define CP_COMMIT() asm volatile("cp.async.commit_group;" ::: "memory")
#define CP_WAIT0()  asm volatile("cp.async.wait_group 0;" ::: "memory")
__device__ __forceinline__ unsigned pack2h(float a, float b) {
    __half ah = __float2half_rn(a), bh = __float2half_rn(b);
    return (unsigned)__half_as_ushort(ah) | ((unsigned)__half_as_ushort(bh) << 16);
}
__device__ __forceinline__ void read_stats(const float* part, int win, int pstride, int nparts,
                                           float& mean, float& rstd) {
    float S = 0.f, Q = 0.f;
    for (int i = 0; i < nparts; ++i) { S += part[win*pstride + i*2]; Q += part[win*pstride + i*2 + 1]; }
    mean = S * (1.f / 32768.f);
    float var = Q * (1.f / 32768.f) - mean * mean;
    rstd = rsqrtf(var + 1e-5f);
}

// ---- shuffle-stencil GN+mix: 4 consecutive channels per warp ---------------
__device__ __forceinline__ void gn_mix_chans(
        int win, int cbase, int lane, float mean, float rstd,
        const float* __restrict__ in, const float* __restrict__ basep,
        const float* __restrict__ gw, const float* __restrict__ gb,
        const float* __restrict__ ls, float* __restrict__ outf,
        float& s2, float& q2, bool want_stats) {
    int p0 = lane * 4;
    int y = lane >> 2, x0 = (lane & 3) * 4;
    float vcnt = 3.f - (y == 0 ? 1.f : 0.f) - (y == 7 ? 1.f : 0.f);
    float rinv[4];
#pragma unroll
    for (int j = 0; j < 4; ++j) {
        int x = x0 + j;
        float hc = 3.f - (x == 0 ? 1.f : 0.f) - (x == 15 ? 1.f : 0.f);
        rinv[j] = 1.f / (hc * vcnt);
    }
#pragma unroll
    for (int ci = 0; ci < 4; ++ci) {
        int c = cbase + ci;
        size_t gi = (size_t)win * WSZ + c * 128 + p0;
        float w = gw[c], bb = gb[c];
        float4 v = *(const float4*)(in + gi);
        v.x = (v.x - mean) * rstd * w + bb;
        v.y = (v.y - mean) * rstd * w + bb;
        v.z = (v.z - mean) * rstd * w + bb;
        v.w = (v.w - mean) * rstd * w + bb;
        float L = __shfl_up_sync(0xffffffffu, v.w, 1);
        float R = __shfl_down_sync(0xffffffffu, v.x, 1);
        if (x0 == 0)  L = 0.f;
        if (x0 == 12) R = 0.f;
        float4 h;
        h.x = L + v.x + v.y;
        h.y = v.x + v.y + v.z;
        h.z = v.y + v.z + v.w;
        h.w = v.z + v.w + R;
        float4 up, dn;
        up.x = __shfl_up_sync(0xffffffffu, h.x, 4);
        up.y = __shfl_up_sync(0xffffffffu, h.y, 4);
        up.z = __shfl_up_sync(0xffffffffu, h.z, 4);
        up.w = __shfl_up_sync(0xffffffffu, h.w, 4);
        dn.x = __shfl_down_sync(0xffffffffu, h.x, 4);
        dn.y = __shfl_down_sync(0xffffffffu, h.y, 4);
        dn.z = __shfl_down_sync(0xffffffffu, h.z, 4);
        dn.w = __shfl_down_sync(0xffffffffu, h.w, 4);
        if (y == 0) { up.x = up.y = up.z = up.w = 0.f; }
        if (y == 7) { dn.x = dn.y = dn.z = dn.w = 0.f; }
        float o0 = (up.x + h.x + dn.x) * rinv[0] - v.x;
        float o1 = (up.y + h.y + dn.y) * rinv[1] - v.y;
        float o2 = (up.z + h.z + dn.z) * rinv[2] - v.z;
        float o3 = (up.w + h.w + dn.w) * rinv[3] - v.w;
        float4 bv = *(const float4*)(basep + gi);
        float lsv = ls[c];
        float4 ov = {bv.x + lsv * o0, bv.y + lsv * o1,
                     bv.z + lsv * o2, bv.w + lsv * o3};
        *(float4*)(outf + gi) = ov;
        if (want_stats) {
            s2 += ov.x + ov.y + ov.z + ov.w;
            q2 += ov.x*ov.x + ov.y*ov.y + ov.z*ov.z + ov.w*ov.w;
        }
    }
}

// ---------------- partition (merged src + qf, fused qf stats) ----------------
__global__ void partition_kernel(const float* __restrict__ src, const float* __restrict__ qf,
                                 __half* __restrict__ memh, __half* __restrict__ tgth,
                                 float* __restrict__ tgt, float* __restrict__ p0) {
    __shared__ float red[16];
    int gb = blockIdx.x;
    bool isq = gb >= 32768;
    int g = (isq ? gb - 32768 : gb) * 256 + threadIdx.x;
    int idx = g * 2;
    int p = idx & 127, c = (idx >> 7) & 255, bw = idx >> 15;
    int b = bw >> 7, wblk = bw & 127;
    int h = (wblk >> 3) * 8 + (p >> 4), w = (wblk & 7) * 16 + (p & 15);
    const float* s = (isq ? qf : src) + (((size_t)b * 256 + c) * 128 + h) * 128 + w;
    float a0 = s[0], a1 = s[1];
    unsigned u = pack2h(a0, a1);
    if (isq) {
        *(unsigned*)(tgth + idx) = u;
        *(float2*)(tgt + idx) = make_float2(a0, a1);
        int tid = threadIdx.x, lane = tid & 31, wid = tid >> 5;
        float ss = a0 + a1, qq = a0*a0 + a1*a1;
#pragma unroll
        for (int off = 16; off; off >>= 1) {
            ss += __shfl_down_sync(0xffffffffu, ss, off);
            qq += __shfl_down_sync(0xffffffffu, qq, off);
        }
        if (lane == 0) { red[wid] = ss; red[8 + wid] = qq; }
        __syncthreads();
        if (tid == 0) {
            float ts = 0.f, tq = 0.f;
#pragma unroll
            for (int i = 0; i < 8; ++i) { ts += red[i]; tq += red[8 + i]; }
            int sb = gb - 32768;
            int win = sb >> 6, slot = sb & 63;
            p0[win*128 + slot*2] = ts; p0[win*128 + slot*2 + 1] = tq;
        }
    } else {
        *(unsigned*)(memh + idx) = u;
    }
}

// ---------------- all weights fp32 -> single fp16 (one launch) --------------
__global__ void conv_w_all(const float* __restrict__ qw, const float* __restrict__ kw,
                           const float* __restrict__ vw, const float* __restrict__ fc1w,
                           const float* __restrict__ fc2w, __half* __restrict__ hi) {
    int g = blockIdx.x * 256 + threadIdx.x;
    int l = g / 57344, r = g - l * 57344;
    const float* srcp;
    size_t oo;
    if (r < 8192)        { srcp = qw  + (size_t)l*65536  + (size_t)r*8;          oo = (size_t)l*458752 + (size_t)r*8; }
    else if (r < 16384)  { srcp = kw  + (size_t)l*65536  + (size_t)(r-8192)*8;   oo = (size_t)l*458752 + 65536  + (size_t)(r-8192)*8; }
    else if (r < 24576)  { srcp = vw  + (size_t)l*65536  + (size_t)(r-16384)*8;  oo = (size_t)l*458752 + 131072 + (size_t)(r-16384)*8; }
    else if (r < 40960)  { srcp = fc1w+ (size_t)l*131072 + (size_t)(r-24576)*8;  oo = (size_t)l*458752 + 196608 + (size_t)(r-24576)*8; }
    else                 { srcp = fc2w+ (size_t)l*131072 + (size_t)(r-40960)*8;  oo = (size_t)l*458752 + 327680 + (size_t)(r-40960)*8; }
    unsigned hh[4];
#pragma unroll
    for (int j = 0; j < 4; ++j) hh[j] = pack2h(srcp[2*j], srcp[2*j+1]);
    uint4 vh = {hh[0], hh[1], hh[2], hh[3]};
    *(uint4*)(hi + oo) = vh;
}

// ---------------- final GN + fused window-reverse transpose ------------------
__global__ __launch_bounds__(256)
void gn_final_apply(const float* __restrict__ in, const float* __restrict__ part, int nparts,
                    const float* __restrict__ gw, const float* __restrict__ gb,
                    float* __restrict__ out) {
    __shared__ float tile[32 * 129];
    int win = blockIdx.x, yb = blockIdx.y, tid = threadIdx.x, lane = tid & 31, wid = tid >> 5;
    float mean, rstd;
    read_stats(part, win, 16, nparts, mean, rstd);
    size_t b0 = (size_t)win * WSZ + yb * 4096;
    const float4* src = (const float4*)(in + b0);
#pragma unroll
    for (int k = 0; k < 4; ++k) {
        int idx = tid + k * 256;
        int cl = idx >> 5, p4 = idx & 31;
        float w = gw[yb * 32 + cl], bb = gb[yb * 32 + cl];
        float4 v = src[idx];
        float* t = tile + cl * 129 + p4 * 4;
        t[0] = (v.x - mean) * rstd * w + bb;
        t[1] = (v.y - mean) * rstd * w + bb;
        t[2] = (v.z - mean) * rstd * w + bb;
        t[3] = (v.w - mean) * rstd * w + bb;
    }
    __syncthreads();
    int b = win >> 7, wblk = win & 127;
    int hb = (wblk >> 3) * 8, wb = (wblk & 7) * 16;
#pragma unroll
    for (int k = 0; k < 16; ++k) {
        int p = k * 8 + wid;
        int h = hb + (p >> 4), w = wb + (p & 15);
        int n = h * 128 + w;
        out[((size_t)n * 4 + b) * 256 + yb * 32 + lane] = tile[lane * 129 + p];
    }
}

// ---------------- tensor-core GEMM (cp.async double-buffered) ----------------
// mode 0: merged QKV + gn_mix1 slices (ob>=6)  mode 1: fc1 (X=hinh)  mode 2: fc2
__global__ __launch_bounds__(256, 2)
void gemm_tc_kernel(const __half* __restrict__ Wh,
                    const __half* __restrict__ Xa, const __half* __restrict__ Xb,
                    const float* __restrict__ b0p, const float* __restrict__ b1p,
                    const float* __restrict__ b2p,
                    float* __restrict__ Yf,
                    __half* __restrict__ Yq, __half* __restrict__ Yk, __half* __restrict__ Yv,
                    int CIN, int mode,
                    const float* __restrict__ base, const float* __restrict__ ls,
                    float* __restrict__ partials,
                    const float* __restrict__ mixIn, const float* __restrict__ mixBase,
                    const float* __restrict__ mixPart, int mixPstride, int mixNparts,
                    const float* __restrict__ mixGw, const float* __restrict__ mixGb,
                    const float* __restrict__ mixLs, float* __restrict__ mixOut) {
    extern __shared__ __half sb[];
    int win = blockIdx.x, ob = blockIdx.y;
    int tid = threadIdx.x, lane = tid & 31, wid = tid >> 5;

    if (mode == 0 && ob >= 6) {
        float mean, rstd, du0 = 0.f, du1 = 0.f;
        read_stats(mixPart, win, mixPstride, mixNparts, mean, rstd);
        gn_mix_chans(win, (ob - 6) * 32 + wid * 4, lane, mean, rstd, mixIn, mixBase,
                     mixGw, mixGb, mixLs, mixOut, du0, du1, false);
        return;
    }

    __half* sWb[2] = { sb, sb + 17920 };
    __half* sXb[2] = { sb + 9216, sb + 17920 + 9216 };
    int wr = wid >> 1, wc = wid & 1;

    const __half* gW = Wh + (size_t)ob * 128 * CIN;
    const __half* X;
    __half* outH;
    const float* bias;
    int O, O0;
    if (mode == 0) {
        int mat = ob >> 1;
        X = (mat == 0) ? Xa : Xb;
        bias = (mat == 0) ? b0p : (mat == 1 ? b1p : b2p);
        outH = (mat == 0) ? Yq : (mat == 1 ? Yk : Yv);
        O = 256; O0 = (ob & 1) * 128;
    } else if (mode == 1) {
        X = Xa; bias = b0p;
        O = 512; O0 = ob * 128;
        outH = Yq;
    } else {
        X = Xa; bias = b0p;
        O = 256; O0 = ob * 128;
        outH = Yq;
    }
    const uint4* gX4 = (const uint4*)X + (size_t)win * CIN * 16;

    auto stage = [&](int t, int buf) {
        int kc = t << 6;
        __half* sW = sWb[buf];
        __half* sX = sXb[buf];
#pragma unroll
        for (int i = tid; i < 1024; i += 256) {
            int r = i >> 3, c4 = i & 7;
            CP_ASYNC16(smem_u32(sW + r * 72 + c4 * 8), gW + (size_t)r * CIN + kc + c4 * 8);
        }
#pragma unroll
        for (int i = tid; i < 1024; i += 256) {
            int r = i >> 4, c4 = i & 15;
            CP_ASYNC16(smem_u32(sX + r * 136 + c4 * 8), gX4 + (kc + r) * 16 + c4);
        }
        CP_COMMIT();
    };

    float acc[2][8][4];
#pragma unroll
    for (int mt = 0; mt < 2; ++mt)
#pragma unroll
        for (int nt = 0; nt < 8; ++nt)
#pragma unroll
            for (int e = 0; e < 4; ++e) acc[mt][nt][e] = 0.f;

    int aRow = (lane & 15), aCol = (lane >> 4) * 8;
    int brbase = ((lane >> 3) & 1) * 8 + (lane & 7);
    int bcofs  = (lane >> 4) * 8;
    int nkc = CIN >> 6;

    stage(0, 0);
    for (int t = 0; t < nkc; ++t) {
        CP_WAIT0();
        __syncthreads();
        if (t + 1 < nkc) stage(t + 1, (t + 1) & 1);
        const __half* sW = sWb[t & 1];
        const __half* sX = sXb[t & 1];
#pragma unroll
        for (int ks = 0; ks < 4; ++ks) {
            unsigned aW[2][4];
#pragma unroll
            for (int mt = 0; mt < 2; ++mt) {
                int ro = (wr * 32 + mt * 16 + aRow) * 72 + ks * 16 + aCol;
                LDSM_X4(aW[mt][0], aW[mt][1], aW[mt][2], aW[mt][3], smem_u32(sW + ro));
            }
#pragma unroll
            for (int np = 0; np < 4; ++np) {
                int bo = (ks * 16 + brbase) * 136 + wc * 64 + np * 16 + bcofs;
                unsigned bX[4];
                LDSM_X4_T(bX[0], bX[1], bX[2], bX[3], smem_u32(sX + bo));
#pragma unroll
                for (int mt = 0; mt < 2; ++mt) {
                    mma_f16(acc[mt][np*2],   aW[mt], bX);
                    mma_f16(acc[mt][np*2+1], aW[mt], bX + 2);
                }
            }
        }
    }

    float ssum = 0.f, ssq = 0.f;
#pragma unroll
    for (int mt = 0; mt < 2; ++mt)
#pragma unroll
        for (int nt = 0; nt < 8; ++nt) {
            int p = wc * 64 + nt * 8 + (lane & 3) * 2;
#pragma unroll
            for (int half = 0; half < 2; ++half) {
                int o = O0 + wr * 32 + mt * 16 + (lane >> 2) + half * 8;
                float bv = bias[o];
                float2 v;
                v.x = acc[mt][nt][half * 2]     + bv;
                v.y = acc[mt][nt][half * 2 + 1] + bv;
                size_t gi = ((size_t)win * O + o) * 128 + p;
                if (mode == 1) {
                    v.x = 0.5f * v.x * (1.f + erff(v.x * 0.70710678118654752f));
                    v.y = 0.5f * v.y * (1.f + erff(v.y * 0.70710678118654752f));
                } else if (mode == 2) {
                    float lsv = ls[o];
                    float2 b2 = *(const float2*)(base + gi);
                    v.x = b2.x + lsv * v.x;
                    v.y = b2.y + lsv * v.y;
                    *(float2*)(Yf + gi) = v;
                    ssum += v.x + v.y;
                    ssq  += v.x*v.x + v.y*v.y;
                }
                *(unsigned*)(outH + gi) = pack2h(v.x, v.y);
            }
        }

    if (mode == 2) {
        __syncthreads();
        float* red = (float*)sb;
#pragma unroll
        for (int off = 16; off; off >>= 1) {
            ssum += __shfl_down_sync(0xffffffffu, ssum, off);
            ssq  += __shfl_down_sync(0xffffffffu, ssq,  off);
        }
        if (lane == 0) { red[wid] = ssum; red[8 + wid] = ssq; }
        __syncthreads();
        if (tid == 0) {
            float ts = 0.f, tq = 0.f;
#pragma unroll
            for (int i = 0; i < 8; ++i) { ts += red[i]; tq += red[8 + i]; }
            partials[win*16 + ob*2] = ts; partials[win*16 + ob*2 + 1] = tq;
        }
    }
}

// ---------------- attention (512 threads) + fused mix2 + gn2->hin ------------
__global__ __launch_bounds__(512, 1)
void attn_kernel(const __half* __restrict__ Qh, const __half* __restrict__ Kh,
                 const __half* __restrict__ Vh,
                 const float* __restrict__ tgt2, float* __restrict__ tgt3,
                 const float* __restrict__ g1w, const float* __restrict__ g1b,
                 const float* __restrict__ ls2,
                 const float* __restrict__ g2w, const float* __restrict__ g2b,
                 __half* __restrict__ hinh) {
    extern __shared__ __half sat[];
    __half* sQb[2] = { sat, sat + 18432 };
    __half* sKb[2] = { sat + 9216, sat + 18432 + 9216 };
    __half* sP = sat;                                  // [128][136]
    __half* sV = sat + 17408;                          // [128][136]
    __shared__ float sM[2][128], sSm[2][128];
    __shared__ float ared[32];
    __shared__ float stats2[2];
    int win = blockIdx.x;
    int tid = threadIdx.x, lane = tid & 31, wid = tid >> 5;
    int wr = wid >> 1, wc = wid & 1;

    const uint4* gQ = (const uint4*)Qh + (size_t)win * 4096;
    const uint4* gK = (const uint4*)Kh + (size_t)win * 4096;
    const uint4* gV = (const uint4*)Vh + (size_t)win * 4096;

    auto stage_s = [&](int ch, int buf) {
        __half* sQ = sQb[buf];
        __half* sK = sKb[buf];
#pragma unroll
        for (int i = tid; i < 1024; i += 512) {
            int r = i >> 3, c4 = i & 7;
            int gi = r * 32 + ch * 8 + c4;
            int so = r * 72 + c4 * 8;
            CP_ASYNC16(smem_u32(sQ + so), gQ + gi);
            CP_ASYNC16(smem_u32(sK + so), gK + gi);
        }
        CP_COMMIT();
    };
    auto stage_v = [&](int cv) {
#pragma unroll
        for (int i = tid; i < 2048; i += 512) {
            int r = i >> 4, c4 = i & 15;
            CP_ASYNC16(smem_u32(sV + r * 136 + c4 * 8), gV + r * 32 + cv * 16 + c4);
        }
        CP_COMMIT();
    };

    float acc[8][4];
#pragma unroll
    for (int j = 0; j < 8; ++j)
#pragma unroll
        for (int e = 0; e < 4; ++e) acc[j][e] = 0.f;

    int aRow = lane & 15, aCol = (lane >> 4) * 8;
    int kRow = (lane & 7) + ((lane >> 4) & 1) * 8;
    int kCol = ((lane >> 3) & 1) * 8;
    int tRow = ((lane >> 3) & 1) * 8 + (lane & 7);
    int tCol = (lane >> 4) * 8;
    int rr = lane >> 2;

    // ---- S = Q @ K^T over 4 chunks of 64 channels ----
    stage_s(0, 0);
    for (int ch = 0; ch < 4; ++ch) {
        CP_WAIT0();
        __syncthreads();
        if (ch + 1 < 4) stage_s(ch + 1, (ch + 1) & 1);
        const __half* sQ = sQb[ch & 1];
        const __half* sK = sKb[ch & 1];
#pragma unroll
        for (int ks = 0; ks < 4; ++ks) {
            unsigned aQ[4];
            int ro = (wr * 16 + aRow) * 72 + ks * 16 + aCol;
            LDSM_X4(aQ[0], aQ[1], aQ[2], aQ[3], smem_u32(sQ + ro));
#pragma unroll
            for (int ngl = 0; ngl < 4; ++ngl) {
                int bo = ((wc * 4 + ngl) * 16 + kRow) * 72 + ks * 16 + kCol;
                unsigned bK[4];
                LDSM_X4(bK[0], bK[1], bK[2], bK[3], smem_u32(sK + bo));
                mma_f16(acc[ngl*2],   aQ, bK);
                mma_f16(acc[ngl*2+1], aQ, bK + 2);
            }
        }
    }

    // ---- softmax (cross-warp over col-halves) ----
    float mx0 = -1e30f, mx1 = -1e30f;
#pragma unroll
    for (int j = 0; j < 8; ++j) {
        mx0 = fmaxf(mx0, fmaxf(acc[j][0], acc[j][1]));
        mx1 = fmaxf(mx1, fmaxf(acc[j][2], acc[j][3]));
    }
#pragma unroll
    for (int off = 1; off <= 2; off <<= 1) {
        mx0 = fmaxf(mx0, __shfl_xor_sync(0xffffffffu, mx0, off));
        mx1 = fmaxf(mx1, __shfl_xor_sync(0xffffffffu, mx1, off));
    }
    if ((lane & 3) == 0) {
        sM[wc][wr * 16 + rr] = mx0;
        sM[wc][wr * 16 + rr + 8] = mx1;
    }
    __syncthreads();
    stage_v(0);
    mx0 = fmaxf(mx0, sM[wc ^ 1][wr * 16 + rr]);
    mx1 = fmaxf(mx1, sM[wc ^ 1][wr * 16 + rr + 8]);
    float s0 = 0.f, s1 = 0.f;
#pragma unroll
    for (int j = 0; j < 8; ++j) {
        acc[j][0] = expf(acc[j][0] - mx0); s0 += acc[j][0];
        acc[j][1] = expf(acc[j][1] - mx0); s0 += acc[j][1];
        acc[j][2] = expf(acc[j][2] - mx1); s1 += acc[j][2];
        acc[j][3] = expf(acc[j][3] - mx1); s1 += acc[j][3];
    }
#pragma unroll
    for (int off = 1; off <= 2; off <<= 1) {
        s0 += __shfl_xor_sync(0xffffffffu, s0, off);
        s1 += __shfl_xor_sync(0xffffffffu, s1, off);
    }
    if ((lane & 3) == 0) {
        sSm[wc][wr * 16 + rr] = s0;
        sSm[wc][wr * 16 + rr + 8] = s1;
    }
    __syncthreads();
    float i0 = 1.f / (s0 + sSm[wc ^ 1][wr * 16 + rr]);
    float i1 = 1.f / (s1 + sSm[wc ^ 1][wr * 16 + rr + 8]);

    // ---- store P (fp16) into smem [128][136] ----
#pragma unroll
    for (int ngl = 0; ngl < 4; ++ngl)
#pragma unroll
        for (int h = 0; h < 2; ++h) {
            int j = ngl * 2 + h;
            int cb = wc * 64 + ngl * 16 + h * 8 + (lane & 3) * 2;
            int r0 = wr * 16 + rr;
            *(unsigned*)(sP + r0 * 136 + cb)       = pack2h(acc[j][0] * i0, acc[j][1] * i0);
            *(unsigned*)(sP + (r0 + 8) * 136 + cb) = pack2h(acc[j][2] * i1, acc[j][3] * i1);
        }
    CP_WAIT0();
    __syncthreads();

    // ---- O = P @ V over 2 cv chunks ----
    float ssum = 0.f, ssq = 0.f;
    for (int cv = 0; cv < 2; ++cv) {
        if (cv == 1) {
            __syncthreads();
            stage_v(1);
            CP_WAIT0();
            __syncthreads();
        }
        float oacc[8][4];
#pragma unroll
        for (int j = 0; j < 8; ++j)
#pragma unroll
            for (int e = 0; e < 4; ++e) oacc[j][e] = 0.f;
#pragma unroll
        for (int mk = 0; mk < 8; ++mk) {
            unsigned aP[4];
            int ro = (wr * 16 + aRow) * 136 + mk * 16 + aCol;
            LDSM_X4(aP[0], aP[1], aP[2], aP[3], smem_u32(sP + ro));
#pragma unroll
            for (int ngl = 0; ngl < 4; ++ngl) {
                int bo = (mk * 16 + tRow) * 136 + wc * 64 + ngl * 16 + tCol;
                unsigned vV[4];
                LDSM_X4_T(vV[0], vV[1], vV[2], vV[3], smem_u32(sV + bo));
                mma_f16(oacc[ngl*2],   aP, vV);
                mma_f16(oacc[ngl*2+1], aP, vV + 2);
            }
        }
#pragma unroll
        for (int j = 0; j < 8; ++j) {
            int col = cv * 128 + wc * 64 + j * 8 + (lane & 3) * 2;
            int n0 = wr * 16 + rr;
            size_t gi = (size_t)win * WSZ + n0 * 256 + col;
            float2 b0 = *(const float2*)(tgt2 + gi);
            float2 r0 = {b0.x + oacc[j][0], b0.y + oacc[j][1]};
            *(float2*)(tgt3 + gi) = r0;
            size_t gi1 = gi + 8 * 256;
            float2 b1 = *(const float2*)(tgt2 + gi1);
            float2 r1 = {b1.x + oacc[j][2], b1.y + oacc[j][3]};
            *(float2*)(tgt3 + gi1) = r1;
            ssum += r0.x + r0.y + r1.x + r1.y;
            ssq  += r0.x*r0.x + r0.y*r0.y + r1.x*r1.x + r1.y*r1.y;
        }
    }

    // ---- stats of attn tgt3 (for gn1 of mix2) ----
#pragma unroll
    for (int off = 16; off; off >>= 1) {
        ssum += __shfl_down_sync(0xffffffffu, ssum, off);
        ssq  += __shfl_down_sync(0xffffffffu, ssq,  off);
    }
    if (lane == 0) { ared[wid] = ssum; ared[16 + wid] = ssq; }
    __syncthreads();
    if (tid == 0) {
        float ts = 0.f, tq = 0.f;
#pragma unroll
        for (int i = 0; i < 16; ++i) { ts += ared[i]; tq += ared[16 + i]; }
        float mean = ts * (1.f / 32768.f);
        float var  = tq * (1.f / 32768.f) - mean * mean;
        stats2[0] = mean; stats2[1] = rsqrtf(var + 1e-5f);
    }
    __syncthreads();
    float mean2 = stats2[0], rstd2 = stats2[1];

    // ---- fused mix2 across 16 warps ----
    float s3 = 0.f, q3 = 0.f;
    for (int yb = 0; yb < 4; ++yb)
        gn_mix_chans(win, yb * 64 + wid * 4, lane, mean2, rstd2, tgt3, tgt2,
                     g1w, g1b, ls2, tgt3, s3, q3, true);
#pragma unroll
    for (int off = 16; off; off >>= 1) {
        s3 += __shfl_down_sync(0xffffffffu, s3, off);
        q3 += __shfl_down_sync(0xffffffffu, q3, off);
    }
    if (lane == 0) { ared[wid] = s3; ared[16 + wid] = q3; }
    __syncthreads();
    if (tid == 0) {
        float ts = 0.f, tq = 0.f;
#pragma unroll
        for (int i = 0; i < 16; ++i) { ts += ared[i]; tq += ared[16 + i]; }
        float mean = ts * (1.f / 32768.f);
        float var  = tq * (1.f / 32768.f) - mean * mean;
        stats2[0] = mean; stats2[1] = rsqrtf(var + 1e-5f);
    }
    __syncthreads();
    float mean3 = stats2[0], rstd3 = stats2[1];

    // ---- gn2 apply: hin = gn2(tgt3) -> fp16 (tgt3 is L2-hot) ----
    int p0 = lane * 4;
    for (int yb = 0; yb < 4; ++yb) {
#pragma unroll
        for (int ci = 0; ci < 4; ++ci) {
            int c = yb * 64 + wid * 4 + ci;
            size_t gi = (size_t)win * WSZ + c * 128 + p0;
            float w = g2w[c], bb = g2b[c];
            float4 v = *(const float4*)(tgt3 + gi);
            v.x = (v.x - mean3) * rstd3 * w + bb;
            v.y = (v.y - mean3) * rstd3 * w + bb;
            v.z = (v.z - mean3) * rstd3 * w + bb;
            v.w = (v.w - mean3) * rstd3 * w + bb;
            uint2 u = {pack2h(v.x, v.y), pack2h(v.z, v.w)};
            *(uint2*)(hinh + gi) = u;
        }
    }
}

// ---------------- host orchestration ---------------------------------------
extern "C" void kernel_launch(void* const* d_in, const int* in_sizes, int n_in,
                              void* d_out, int out_size) {
    const float* src  = (const float*)d_in[0];
    const float* qf   = (const float*)d_in[1];
    const float* gn1w = (const float*)d_in[2];
    const float* gn1b = (const float*)d_in[3];
    const float* gn2w = (const float*)d_in[4];
    const float* gn2b = (const float*)d_in[5];
    const float* ls1  = (const float*)d_in[6];
    const float* ls2  = (const float*)d_in[7];
    const float* ls3  = (const float*)d_in[8];
    const float* qw   = (const float*)d_in[9];
    const float* qb   = (const float*)d_in[10];
    const float* kw   = (const float*)d_in[11];
    const float* kb   = (const float*)d_in[12];
    const float* vw   = (const float*)d_in[13];
    const float* vb   = (const float*)d_in[14];
    const float* fc1w = (const float*)d_in[15];
    const float* fc1b = (const float*)d_in[16];
    const float* fc2w = (const float*)d_in[17];
    const float* fc2b = (const float*)d_in[18];
    const float* gnfw = (const float*)d_in[19];
    const float* gnfb = (const float*)d_in[20];
    float* out = (float*)d_out;

    float *tgt, *tgt2, *tgt3, *p0, *p1;
    __half *memh, *tgth, *qh, *kh, *vh, *hinh, *hh, *wh;
    cudaGetSymbolAddress((void**)&tgt,  g_tgt);
    cudaGetSymbolAddress((void**)&tgt2, g_tgt2);
    cudaGetSymbolAddress((void**)&tgt3, g_tgt3);
    cudaGetSymbolAddress((void**)&p0,   g_p0);
    cudaGetSymbolAddress((void**)&p1,   g_p1);
    cudaGetSymbolAddress((void**)&memh, g_memh);
    cudaGetSymbolAddress((void**)&tgth, g_tgth);
    cudaGetSymbolAddress((void**)&qh,   g_qh);
    cudaGetSymbolAddress((void**)&kh,   g_kh);
    cudaGetSymbolAddress((void**)&vh,   g_vh);
    cudaGetSymbolAddress((void**)&hinh, g_hinh);
    cudaGetSymbolAddress((void**)&hh,   g_hh);
    cudaGetSymbolAddress((void**)&wh,   g_wh);

    const int SM_ATTN = 73728;
    const int SM_TC   = 71680;
    cudaFuncSetAttribute(attn_kernel,    cudaFuncAttributeMaxDynamicSharedMemorySize, SM_ATTN);
    cudaFuncSetAttribute(gemm_tc_kernel, cudaFuncAttributeMaxDynamicSharedMemorySize, SM_TC);

    partition_kernel<<<65536, 256>>>(src, qf, memh, tgth, tgt, p0);
    conv_w_all<<<448, 256>>>(qw, kw, vw, fc1w, fc2w, wh);

    for (int l = 0; l < 2; ++l) {
        int lC = l * CDIM;
        size_t lb = (size_t)l * 458752;
        const float* mp = (l == 0) ? p0 : p1;
        int mstride = (l == 0) ? 128 : 16;
        int mnp = (l == 0) ? 64 : 2;
        // merged: QKV gemm (ob<6) + gn_mix1 tgt->tgt2 (ob 6..13)
        gemm_tc_kernel<<<dim3(NW,14), 256, SM_TC>>>(wh + lb,
            tgth, memh, qb + lC, kb + lC, vb + lC,
            nullptr, qh, kh, vh, 256, 0, nullptr, nullptr, nullptr,
            tgt, tgt, mp, mstride, mnp, gn1w + lC, gn1b + lC, ls1 + lC, tgt2);
        // attn + mix2 + gn2: tgt3 final, hinh = fp16 gn2(tgt3)
        attn_kernel<<<NW, 512, SM_ATTN>>>(qh, kh, vh, tgt2, tgt3,
                                          gn1w + lC, gn1b + lC, ls2 + lC,
                                          gn2w + lC, gn2b + lC, hinh);
        // h = gelu(fc1(hin))
        gemm_tc_kernel<<<dim3(NW,4), 256, SM_TC>>>(wh + lb + 196608,
            hinh, nullptr, fc1b + (size_t)l*512, nullptr, nullptr,
            nullptr, hh, nullptr, nullptr, 256, 1, nullptr, nullptr, nullptr,
            nullptr, nullptr, nullptr, 0, 0, nullptr, nullptr, nullptr, nullptr);
        // tgt = tgt3 + ls3*fc2(h)  (+stats -> p1)
        gemm_tc_kernel<<<dim3(NW,2), 256, SM_TC>>>(wh + lb + 327680,
            hh, nullptr, fc2b + lC, nullptr, nullptr,
            tgt, tgth, nullptr, nullptr, 512, 2, tgt3, ls3 + lC, p1,
            nullptr, nullptr, nullptr, 0, 0, nullptr, nullptr, nullptr, nullptr);
    }

    gn_final_apply<<<dim3(NW,8), 256>>>(tgt, p1, 2, gnfw, gnfb, out);
}

// round 17
// speedup vs baseline: 1.0933x; 1.0286x over previous
#include <cuda_runtime.h>
#include <cuda_fp16.h>
#include <math.h>
#include <stdint.h>

#define NW   512
#define CDIM 256
#define PDIM 128
#define WSZ  (CDIM*PDIM)

// ---------------- scratch (static device globals; no allocations) ----------
__device__ float g_tgt [NW*WSZ];
__device__ __half g_tgt2h[NW*WSZ];
__device__ __half g_tgt3h[NW*WSZ];
__device__ __half g_memh[NW*WSZ];
__device__ __half g_tgth[NW*WSZ];
__device__ __half g_qh [NW*WSZ];
__device__ __half g_kh [NW*WSZ];
__device__ __half g_vh [NW*WSZ];
__device__ __half g_hinh[NW*WSZ];
__device__ __half g_hh [NW*2*WSZ];
__device__ __half g_wh[2*458752];
__device__ float g_p0[NW*128];
__device__ float g_p1[NW*16];

// ================= helpers =================================================
__device__ __forceinline__ uint32_t smem_u32(const void* p) {
    uint32_t a;
    asm("{ .reg .u64 t; cvta.to.shared.u64 t, %1; cvt.u32.u64 %0, t; }" : "=r"(a) : "l"(p));
    return a;
}
#define LDSM_X4(r0,r1,r2,r3,addr) \
    asm volatile("ldmatrix.sync.aligned.m8n8.x4.shared.b16 {%0,%1,%2,%3}, [%4];" \
        : "=r"(r0),"=r"(r1),"=r"(r2),"=r"(r3) : "r"(addr))
#define LDSM_X4_T(r0,r1,r2,r3,addr) \
    asm volatile("ldmatrix.sync.aligned.m8n8.x4.trans.shared.b16 {%0,%1,%2,%3}, [%4];" \
        : "=r"(r0),"=r"(r1),"=r"(r2),"=r"(r3) : "r"(addr))
__device__ __forceinline__ void mma_f16(float* d, const unsigned* a, const unsigned* b) {
    asm volatile("mma.sync.aligned.m16n8k16.row.col.f32.f16.f16.f32 "
        "{%0,%1,%2,%3}, {%4,%5,%6,%7}, {%8,%9}, {%0,%1,%2,%3};"
        : "+f"(d[0]),"+f"(d[1]),"+f"(d[2]),"+f"(d[3])
        : "r"(a[0]),"r"(a[1]),"r"(a[2]),"r"(a[3]), "r"(b[0]),"r"(b[1]));
}
#define CP_ASYNC16(sa, gp) \
    asm volatile("cp.async.cg.shared.global [%0], [%1], 16;" :: "r"(sa), "l"(gp))
#define CP_COMMIT() asm volatile("cp.async.commit_group;" ::: "memory")
#define CP_WAIT0()  asm volatile("cp.async.wait_group 0;" ::: "memory")
__device__ __forceinline__ unsigned pack2h(float a, float b) {
    __half ah = __float2half_rn(a), bh = __float2half_rn(b);
    return (unsigned)__half_as_ushort(ah) | ((unsigned)__half_as_ushort(bh) << 16);
}
__device__ __forceinline__ float4 ld4(const float* p) { return *(const float4*)p; }
__device__ __forceinline__ float4 ld4(const __half* p) {
    uint2 u = *(const uint2*)p;
    __half2 a = *(__half2*)&u.x, b = *(__half2*)&u.y;
    float2 fa = __half22float2(a), fb = __half22float2(b);
    return make_float4(fa.x, fa.y, fb.x, fb.y);
}
__device__ __forceinline__ void st4h(__half* p, float4 v) {
    uint2 u = {pack2h(v.x, v.y), pack2h(v.z, v.w)};
    *(uint2*)p = u;
}
__device__ __forceinline__ float2 ld2h(const __half* p) {
    unsigned u = *(const unsigned*)p;
    return __half22float2(*(__half2*)&u);
}
__device__ __forceinline__ void read_stats(const float* part, int win, int pstride, int nparts,
                                           float& mean, float& rstd) {
    float S = 0.f, Q = 0.f;
    for (int i = 0; i < nparts; ++i) { S += part[win*pstride + i*2]; Q += part[win*pstride + i*2 + 1]; }
    mean = S * (1.f / 32768.f);
    float var = Q * (1.f / 32768.f) - mean * mean;
    rstd = rsqrtf(var + 1e-5f);
}

// ---- shuffle-stencil GN+mix: 4 consecutive channels per warp ---------------
template<typename TI, typename TB>
__device__ __forceinline__ void gn_mix_chans(
        int win, int cbase, int lane, float mean, float rstd,
        const TI* __restrict__ in, const TB* __restrict__ basep,
        const float* __restrict__ gw, const float* __restrict__ gb,
        const float* __restrict__ ls, __half* __restrict__ outf,
        float& s2, float& q2, bool want_stats) {
    int p0 = lane * 4;
    int y = lane >> 2, x0 = (lane & 3) * 4;
    float vcnt = 3.f - (y == 0 ? 1.f : 0.f) - (y == 7 ? 1.f : 0.f);
    float rinv[4];
#pragma unroll
    for (int j = 0; j < 4; ++j) {
        int x = x0 + j;
        float hc = 3.f - (x == 0 ? 1.f : 0.f) - (x == 15 ? 1.f : 0.f);
        rinv[j] = 1.f / (hc * vcnt);
    }
#pragma unroll
    for (int ci = 0; ci < 4; ++ci) {
        int c = cbase + ci;
        size_t gi = (size_t)win * WSZ + c * 128 + p0;
        float w = gw[c], bb = gb[c];
        float4 v = ld4(in + gi);
        v.x = (v.x - mean) * rstd * w + bb;
        v.y = (v.y - mean) * rstd * w + bb;
        v.z = (v.z - mean) * rstd * w + bb;
        v.w = (v.w - mean) * rstd * w + bb;
        float L = __shfl_up_sync(0xffffffffu, v.w, 1);
        float R = __shfl_down_sync(0xffffffffu, v.x, 1);
        if (x0 == 0)  L = 0.f;
        if (x0 == 12) R = 0.f;
        float4 h;
        h.x = L + v.x + v.y;
        h.y = v.x + v.y + v.z;
        h.z = v.y + v.z + v.w;
        h.w = v.z + v.w + R;
        float4 up, dn;
        up.x = __shfl_up_sync(0xffffffffu, h.x, 4);
        up.y = __shfl_up_sync(0xffffffffu, h.y, 4);
        up.z = __shfl_up_sync(0xffffffffu, h.z, 4);
        up.w = __shfl_up_sync(0xffffffffu, h.w, 4);
        dn.x = __shfl_down_sync(0xffffffffu, h.x, 4);
        dn.y = __shfl_down_sync(0xffffffffu, h.y, 4);
        dn.z = __shfl_down_sync(0xffffffffu, h.z, 4);
        dn.w = __shfl_down_sync(0xffffffffu, h.w, 4);
        if (y == 0) { up.x = up.y = up.z = up.w = 0.f; }
        if (y == 7) { dn.x = dn.y = dn.z = dn.w = 0.f; }
        float o0 = (up.x + h.x + dn.x) * rinv[0] - v.x;
        float o1 = (up.y + h.y + dn.y) * rinv[1] - v.y;
        float o2 = (up.z + h.z + dn.z) * rinv[2] - v.z;
        float o3 = (up.w + h.w + dn.w) * rinv[3] - v.w;
        float4 bv = ld4(basep + gi);
        float lsv = ls[c];
        float4 ov = {bv.x + lsv * o0, bv.y + lsv * o1,
                     bv.z + lsv * o2, bv.w + lsv * o3};
        st4h(outf + gi, ov);
        if (want_stats) {
            s2 += ov.x + ov.y + ov.z + ov.w;
            q2 += ov.x*ov.x + ov.y*ov.y + ov.z*ov.z + ov.w*ov.w;
        }
    }
}

// ---------------- partition (merged src + qf, fused qf stats) ----------------
__global__ void partition_kernel(const float* __restrict__ src, const float* __restrict__ qf,
                                 __half* __restrict__ memh, __half* __restrict__ tgth,
                                 float* __restrict__ tgt, float* __restrict__ p0) {
    __shared__ float red[16];
    int gb = blockIdx.x;
    bool isq = gb >= 32768;
    int g = (isq ? gb - 32768 : gb) * 256 + threadIdx.x;
    int idx = g * 2;
    int p = idx & 127, c = (idx >> 7) & 255, bw = idx >> 15;
    int b = bw >> 7, wblk = bw & 127;
    int h = (wblk >> 3) * 8 + (p >> 4), w = (wblk & 7) * 16 + (p & 15);
    const float* s = (isq ? qf : src) + (((size_t)b * 256 + c) * 128 + h) * 128 + w;
    float a0 = s[0], a1 = s[1];
    unsigned u = pack2h(a0, a1);
    if (isq) {
        *(unsigned*)(tgth + idx) = u;
        *(float2*)(tgt + idx) = make_float2(a0, a1);
        int tid = threadIdx.x, lane = tid & 31, wid = tid >> 5;
        float ss = a0 + a1, qq = a0*a0 + a1*a1;
#pragma unroll
        for (int off = 16; off; off >>= 1) {
            ss += __shfl_down_sync(0xffffffffu, ss, off);
            qq += __shfl_down_sync(0xffffffffu, qq, off);
        }
        if (lane == 0) { red[wid] = ss; red[8 + wid] = qq; }
        __syncthreads();
        if (tid == 0) {
            float ts = 0.f, tq = 0.f;
#pragma unroll
            for (int i = 0; i < 8; ++i) { ts += red[i]; tq += red[8 + i]; }
            int sb = gb - 32768;
            int win = sb >> 6, slot = sb & 63;
            p0[win*128 + slot*2] = ts; p0[win*128 + slot*2 + 1] = tq;
        }
    } else {
        *(unsigned*)(memh + idx) = u;
    }
}

// ---------------- all weights fp32 -> single fp16 (one launch) --------------
__global__ void conv_w_all(const float* __restrict__ qw, const float* __restrict__ kw,
                           const float* __restrict__ vw, const float* __restrict__ fc1w,
                           const float* __restrict__ fc2w, __half* __restrict__ hi) {
    int g = blockIdx.x * 256 + threadIdx.x;
    int l = g / 57344, r = g - l * 57344;
    const float* srcp;
    size_t oo;
    if (r < 8192)        { srcp = qw  + (size_t)l*65536  + (size_t)r*8;          oo = (size_t)l*458752 + (size_t)r*8; }
    else if (r < 16384)  { srcp = kw  + (size_t)l*65536  + (size_t)(r-8192)*8;   oo = (size_t)l*458752 + 65536  + (size_t)(r-8192)*8; }
    else if (r < 24576)  { srcp = vw  + (size_t)l*65536  + (size_t)(r-16384)*8;  oo = (size_t)l*458752 + 131072 + (size_t)(r-16384)*8; }
    else if (r < 40960)  { srcp = fc1w+ (size_t)l*131072 + (size_t)(r-24576)*8;  oo = (size_t)l*458752 + 196608 + (size_t)(r-24576)*8; }
    else                 { srcp = fc2w+ (size_t)l*131072 + (size_t)(r-40960)*8;  oo = (size_t)l*458752 + 327680 + (size_t)(r-40960)*8; }
    unsigned hh[4];
#pragma unroll
    for (int j = 0; j < 4; ++j) hh[j] = pack2h(srcp[2*j], srcp[2*j+1]);
    uint4 vh = {hh[0], hh[1], hh[2], hh[3]};
    *(uint4*)(hi + oo) = vh;
}

// ---------------- final GN + fused window-reverse transpose ------------------
__global__ __launch_bounds__(256)
void gn_final_apply(const float* __restrict__ in, const float* __restrict__ part, int nparts,
                    const float* __restrict__ gw, const float* __restrict__ gb,
                    float* __restrict__ out) {
    __shared__ float tile[32 * 129];
    int win = blockIdx.x, yb = blockIdx.y, tid = threadIdx.x, lane = tid & 31, wid = tid >> 5;
    float mean, rstd;
    read_stats(part, win, 16, nparts, mean, rstd);
    size_t b0 = (size_t)win * WSZ + yb * 4096;
    const float4* src = (const float4*)(in + b0);
#pragma unroll
    for (int k = 0; k < 4; ++k) {
        int idx = tid + k * 256;
        int cl = idx >> 5, p4 = idx & 31;
        float w = gw[yb * 32 + cl], bb = gb[yb * 32 + cl];
        float4 v = src[idx];
        float* t = tile + cl * 129 + p4 * 4;
        t[0] = (v.x - mean) * rstd * w + bb;
        t[1] = (v.y - mean) * rstd * w + bb;
        t[2] = (v.z - mean) * rstd * w + bb;
        t[3] = (v.w - mean) * rstd * w + bb;
    }
    __syncthreads();
    int b = win >> 7, wblk = win & 127;
    int hb = (wblk >> 3) * 8, wb = (wblk & 7) * 16;
#pragma unroll
    for (int k = 0; k < 16; ++k) {
        int p = k * 8 + wid;
        int h = hb + (p >> 4), w = wb + (p & 15);
        int n = h * 128 + w;
        out[((size_t)n * 4 + b) * 256 + yb * 32 + lane] = tile[lane * 129 + p];
    }
}

// ---------------- tensor-core GEMM (cp.async double-buffered) ----------------
// mode 0: merged QKV + gn_mix1 slices (ob>=6)  mode 1: fc1 (X=hinh)  mode 2: fc2
__global__ __launch_bounds__(256, 2)
void gemm_tc_kernel(const __half* __restrict__ Wh,
                    const __half* __restrict__ Xa, const __half* __restrict__ Xb,
                    const float* __restrict__ b0p, const float* __restrict__ b1p,
                    const float* __restrict__ b2p,
                    float* __restrict__ Yf,
                    __half* __restrict__ Yq, __half* __restrict__ Yk, __half* __restrict__ Yv,
                    int CIN, int mode,
                    const __half* __restrict__ baseh, const float* __restrict__ ls,
                    float* __restrict__ partials,
                    const float* __restrict__ mixIn, const float* __restrict__ mixBase,
                    const float* __restrict__ mixPart, int mixPstride, int mixNparts,
                    const float* __restrict__ mixGw, const float* __restrict__ mixGb,
                    const float* __restrict__ mixLs, __half* __restrict__ mixOut) {
    extern __shared__ __half sb[];
    int win = blockIdx.x, ob = blockIdx.y;
    int tid = threadIdx.x, lane = tid & 31, wid = tid >> 5;

    if (mode == 0 && ob >= 6) {
        float mean, rstd, du0 = 0.f, du1 = 0.f;
        read_stats(mixPart, win, mixPstride, mixNparts, mean, rstd);
        gn_mix_chans<float, float>(win, (ob - 6) * 32 + wid * 4, lane, mean, rstd,
                                   mixIn, mixBase, mixGw, mixGb, mixLs, mixOut,
                                   du0, du1, false);
        return;
    }

    __half* sWb[2] = { sb, sb + 17920 };
    __half* sXb[2] = { sb + 9216, sb + 17920 + 9216 };
    int wr = wid >> 1, wc = wid & 1;

    const __half* gW = Wh + (size_t)ob * 128 * CIN;
    const __half* X;
    __half* outH;
    const float* bias;
    int O, O0;
    if (mode == 0) {
        int mat = ob >> 1;
        X = (mat == 0) ? Xa : Xb;
        bias = (mat == 0) ? b0p : (mat == 1 ? b1p : b2p);
        outH = (mat == 0) ? Yq : (mat == 1 ? Yk : Yv);
        O = 256; O0 = (ob & 1) * 128;
    } else if (mode == 1) {
        X = Xa; bias = b0p;
        O = 512; O0 = ob * 128;
        outH = Yq;
    } else {
        X = Xa; bias = b0p;
        O = 256; O0 = ob * 128;
        outH = Yq;
    }
    const uint4* gX4 = (const uint4*)X + (size_t)win * CIN * 16;

    auto stage = [&](int t, int buf) {
        int kc = t << 6;
        __half* sW = sWb[buf];
        __half* sX = sXb[buf];
#pragma unroll
        for (int i = tid; i < 1024; i += 256) {
            int r = i >> 3, c4 = i & 7;
            CP_ASYNC16(smem_u32(sW + r * 72 + c4 * 8), gW + (size_t)r * CIN + kc + c4 * 8);
        }
#pragma unroll
        for (int i = tid; i < 1024; i += 256) {
            int r = i >> 4, c4 = i & 15;
            CP_ASYNC16(smem_u32(sX + r * 136 + c4 * 8), gX4 + (kc + r) * 16 + c4);
        }
        CP_COMMIT();
    };

    float acc[2][8][4];
#pragma unroll
    for (int mt = 0; mt < 2; ++mt)
#pragma unroll
        for (int nt = 0; nt < 8; ++nt)
#pragma unroll
            for (int e = 0; e < 4; ++e) acc[mt][nt][e] = 0.f;

    int aRow = (lane & 15), aCol = (lane >> 4) * 8;
    int brbase = ((lane >> 3) & 1) * 8 + (lane & 7);
    int bcofs  = (lane >> 4) * 8;
    int nkc = CIN >> 6;

    stage(0, 0);
    for (int t = 0; t < nkc; ++t) {
        CP_WAIT0();
        __syncthreads();
        if (t + 1 < nkc) stage(t + 1, (t + 1) & 1);
        const __half* sW = sWb[t & 1];
        const __half* sX = sXb[t & 1];
#pragma unroll
        for (int ks = 0; ks < 4; ++ks) {
            unsigned aW[2][4];
#pragma unroll
            for (int mt = 0; mt < 2; ++mt) {
                int ro = (wr * 32 + mt * 16 + aRow) * 72 + ks * 16 + aCol;
                LDSM_X4(aW[mt][0], aW[mt][1], aW[mt][2], aW[mt][3], smem_u32(sW + ro));
            }
#pragma unroll
            for (int np = 0; np < 4; ++np) {
                int bo = (ks * 16 + brbase) * 136 + wc * 64 + np * 16 + bcofs;
                unsigned bX[4];
                LDSM_X4_T(bX[0], bX[1], bX[2], bX[3], smem_u32(sX + bo));
#pragma unroll
                for (int mt = 0; mt < 2; ++mt) {
                    mma_f16(acc[mt][np*2],   aW[mt], bX);
                    mma_f16(acc[mt][np*2+1], aW[mt], bX + 2);
                }
            }
        }
    }

    float ssum = 0.f, ssq = 0.f;
#pragma unroll
    for (int mt = 0; mt < 2; ++mt)
#pragma unroll
        for (int nt = 0; nt < 8; ++nt) {
            int p = wc * 64 + nt * 8 + (lane & 3) * 2;
#pragma unroll
            for (int half = 0; half < 2; ++half) {
                int o = O0 + wr * 32 + mt * 16 + (lane >> 2) + half * 8;
                float bv = bias[o];
                float2 v;
                v.x = acc[mt][nt][half * 2]     + bv;
                v.y = acc[mt][nt][half * 2 + 1] + bv;
                size_t gi = ((size_t)win * O + o) * 128 + p;
                if (mode == 1) {
                    v.x = 0.5f * v.x * (1.f + erff(v.x * 0.70710678118654752f));
                    v.y = 0.5f * v.y * (1.f + erff(v.y * 0.70710678118654752f));
                } else if (mode == 2) {
                    float lsv = ls[o];
                    float2 b2 = ld2h(baseh + gi);
                    v.x = b2.x + lsv * v.x;
                    v.y = b2.y + lsv * v.y;
                    *(float2*)(Yf + gi) = v;
                    ssum += v.x + v.y;
                    ssq  += v.x*v.x + v.y*v.y;
                }
                *(unsigned*)(outH + gi) = pack2h(v.x, v.y);
            }
        }

    if (mode == 2) {
        __syncthreads();
        float* red = (float*)sb;
#pragma unroll
        for (int off = 16; off; off >>= 1) {
            ssum += __shfl_down_sync(0xffffffffu, ssum, off);
            ssq  += __shfl_down_sync(0xffffffffu, ssq,  off);
        }
        if (lane == 0) { red[wid] = ssum; red[8 + wid] = ssq; }
        __syncthreads();
        if (tid == 0) {
            float ts = 0.f, tq = 0.f;
#pragma unroll
            for (int i = 0; i < 8; ++i) { ts += red[i]; tq += red[8 + i]; }
            partials[win*16 + ob*2] = ts; partials[win*16 + ob*2 + 1] = tq;
        }
    }
}

// ---------------- attention (512 threads) + fused mix2 + gn2->hin ------------
__global__ __launch_bounds__(512, 1)
void attn_kernel(const __half* __restrict__ Qh, const __half* __restrict__ Kh,
                 const __half* __restrict__ Vh,
                 const __half* __restrict__ tgt2, __half* __restrict__ tgt3,
                 const float* __restrict__ g1w, const float* __restrict__ g1b,
                 const float* __restrict__ ls2,
                 const float* __restrict__ g2w, const float* __restrict__ g2b,
                 __half* __restrict__ hinh) {
    extern __shared__ __half sat[];
    __half* sQb[2] = { sat, sat + 18432 };
    __half* sKb[2] = { sat + 9216, sat + 18432 + 9216 };
    __half* sP = sat;                                  // [128][136]
    __half* sV = sat + 17408;                          // [128][136]
    __shared__ float sM[2][128], sSm[2][128];
    __shared__ float ared[32];
    __shared__ float stats2[2];
    int win = blockIdx.x;
    int tid = threadIdx.x, lane = tid & 31, wid = tid >> 5;
    int wr = wid >> 1, wc = wid & 1;

    const uint4* gQ = (const uint4*)Qh + (size_t)win * 4096;
    const uint4* gK = (const uint4*)Kh + (size_t)win * 4096;
    const uint4* gV = (const uint4*)Vh + (size_t)win * 4096;

    auto stage_s = [&](int ch, int buf) {
        __half* sQ = sQb[buf];
        __half* sK = sKb[buf];
#pragma unroll
        for (int i = tid; i < 1024; i += 512) {
            int r = i >> 3, c4 = i & 7;
            int gi = r * 32 + ch * 8 + c4;
            int so = r * 72 + c4 * 8;
            CP_ASYNC16(smem_u32(sQ + so), gQ + gi);
            CP_ASYNC16(smem_u32(sK + so), gK + gi);
        }
        CP_COMMIT();
    };
    auto stage_v = [&](int cv) {
#pragma unroll
        for (int i = tid; i < 2048; i += 512) {
            int r = i >> 4, c4 = i & 15;
            CP_ASYNC16(smem_u32(sV + r * 136 + c4 * 8), gV + r * 32 + cv * 16 + c4);
        }
        CP_COMMIT();
    };

    float acc[8][4];
#pragma unroll
    for (int j = 0; j < 8; ++j)
#pragma unroll
        for (int e = 0; e < 4; ++e) acc[j][e] = 0.f;

    int aRow = lane & 15, aCol = (lane >> 4) * 8;
    int kRow = (lane & 7) + ((lane >> 4) & 1) * 8;
    int kCol = ((lane >> 3) & 1) * 8;
    int tRow = ((lane >> 3) & 1) * 8 + (lane & 7);
    int tCol = (lane >> 4) * 8;
    int rr = lane >> 2;

    // ---- S = Q @ K^T over 4 chunks of 64 channels ----
    stage_s(0, 0);
    for (int ch = 0; ch < 4; ++ch) {
        CP_WAIT0();
        __syncthreads();
        if (ch + 1 < 4) stage_s(ch + 1, (ch + 1) & 1);
        const __half* sQ = sQb[ch & 1];
        const __half* sK = sKb[ch & 1];
#pragma unroll
        for (int ks = 0; ks < 4; ++ks) {
            unsigned aQ[4];
            int ro = (wr * 16 + aRow) * 72 + ks * 16 + aCol;
            LDSM_X4(aQ[0], aQ[1], aQ[2], aQ[3], smem_u32(sQ + ro));
#pragma unroll
            for (int ngl = 0; ngl < 4; ++ngl) {
                int bo = ((wc * 4 + ngl) * 16 + kRow) * 72 + ks * 16 + kCol;
                unsigned bK[4];
                LDSM_X4(bK[0], bK[1], bK[2], bK[3], smem_u32(sK + bo));
                mma_f16(acc[ngl*2],   aQ, bK);
                mma_f16(acc[ngl*2+1], aQ, bK + 2);
            }
        }
    }

    // ---- softmax (cross-warp over col-halves) ----
    float mx0 = -1e30f, mx1 = -1e30f;
#pragma unroll
    for (int j = 0; j < 8; ++j) {
        mx0 = fmaxf(mx0, fmaxf(acc[j][0], acc[j][1]));
        mx1 = fmaxf(mx1, fmaxf(acc[j][2], acc[j][3]));
    }
#pragma unroll
    for (int off = 1; off <= 2; off <<= 1) {
        mx0 = fmaxf(mx0, __shfl_xor_sync(0xffffffffu, mx0, off));
        mx1 = fmaxf(mx1, __shfl_xor_sync(0xffffffffu, mx1, off));
    }
    if ((lane & 3) == 0) {
        sM[wc][wr * 16 + rr] = mx0;
        sM[wc][wr * 16 + rr + 8] = mx1;
    }
    __syncthreads();
    stage_v(0);
    mx0 = fmaxf(mx0, sM[wc ^ 1][wr * 16 + rr]);
    mx1 = fmaxf(mx1, sM[wc ^ 1][wr * 16 + rr + 8]);
    float s0 = 0.f, s1 = 0.f;
#pragma unroll
    for (int j = 0; j < 8; ++j) {
        acc[j][0] = expf(acc[j][0] - mx0); s0 += acc[j][0];
        acc[j][1] = expf(acc[j][1] - mx0); s0 += acc[j][1];
        acc[j][2] = expf(acc[j][2] - mx1); s1 += acc[j][2];
        acc[j][3] = expf(acc[j][3] - mx1); s1 += acc[j][3];
    }
#pragma unroll
    for (int off = 1; off <= 2; off <<= 1) {
        s0 += __shfl_xor_sync(0xffffffffu, s0, off);
        s1 += __shfl_xor_sync(0xffffffffu, s1, off);
    }
    if ((lane & 3) == 0) {
        sSm[wc][wr * 16 + rr] = s0;
        sSm[wc][wr * 16 + rr + 8] = s1;
    }
    __syncthreads();
    float i0 = 1.f / (s0 + sSm[wc ^ 1][wr * 16 + rr]);
    float i1 = 1.f / (s1 + sSm[wc ^ 1][wr * 16 + rr + 8]);

    // ---- store P (fp16) into smem [128][136] ----
#pragma unroll
    for (int ngl = 0; ngl < 4; ++ngl)
#pragma unroll
        for (int h = 0; h < 2; ++h) {
            int j = ngl * 2 + h;
            int cb = wc * 64 + ngl * 16 + h * 8 + (lane & 3) * 2;
            int r0 = wr * 16 + rr;
            *(unsigned*)(sP + r0 * 136 + cb)       = pack2h(acc[j][0] * i0, acc[j][1] * i0);
            *(unsigned*)(sP + (r0 + 8) * 136 + cb) = pack2h(acc[j][2] * i1, acc[j][3] * i1);
        }
    CP_WAIT0();
    __syncthreads();

    // ---- O = P @ V over 2 cv chunks ----
    float ssum = 0.f, ssq = 0.f;
    for (int cv = 0; cv < 2; ++cv) {
        if (cv == 1) {
            __syncthreads();
            stage_v(1);
            CP_WAIT0();
            __syncthreads();
        }
        float oacc[8][4];
#pragma unroll
        for (int j = 0; j < 8; ++j)
#pragma unroll
            for (int e = 0; e < 4; ++e) oacc[j][e] = 0.f;
#pragma unroll
        for (int mk = 0; mk < 8; ++mk) {
            unsigned aP[4];
            int ro = (wr * 16 + aRow) * 136 + mk * 16 + aCol;
            LDSM_X4(aP[0], aP[1], aP[2], aP[3], smem_u32(sP + ro));
#pragma unroll
            for (int ngl = 0; ngl < 4; ++ngl) {
                int bo = (mk * 16 + tRow) * 136 + wc * 64 + ngl * 16 + tCol;
                unsigned vV[4];
                LDSM_X4_T(vV[0], vV[1], vV[2], vV[3], smem_u32(sV + bo));
                mma_f16(oacc[ngl*2],   aP, vV);
                mma_f16(oacc[ngl*2+1], aP, vV + 2);
            }
        }
#pragma unroll
        for (int j = 0; j < 8; ++j) {
            int col = cv * 128 + wc * 64 + j * 8 + (lane & 3) * 2;
            int n0 = wr * 16 + rr;
            size_t gi = (size_t)win * WSZ + n0 * 256 + col;
            float2 b0 = ld2h(tgt2 + gi);
            float2 r0 = {b0.x + oacc[j][0], b0.y + oacc[j][1]};
            *(unsigned*)(tgt3 + gi) = pack2h(r0.x, r0.y);
            size_t gi1 = gi + 8 * 256;
            float2 b1 = ld2h(tgt2 + gi1);
            float2 r1 = {b1.x + oacc[j][2], b1.y + oacc[j][3]};
            *(unsigned*)(tgt3 + gi1) = pack2h(r1.x, r1.y);
            ssum += r0.x + r0.y + r1.x + r1.y;
            ssq  += r0.x*r0.x + r0.y*r0.y + r1.x*r1.x + r1.y*r1.y;
        }
    }

    // ---- stats of attn tgt3 (for gn1 of mix2) ----
#pragma unroll
    for (int off = 16; off; off >>= 1) {
        ssum += __shfl_down_sync(0xffffffffu, ssum, off);
        ssq  += __shfl_down_sync(0xffffffffu, ssq,  off);
    }
    if (lane == 0) { ared[wid] = ssum; ared[16 + wid] = ssq; }
    __syncthreads();
    if (tid == 0) {
        float ts = 0.f, tq = 0.f;
#pragma unroll
        for (int i = 0; i < 16; ++i) { ts += ared[i]; tq += ared[16 + i]; }
        float mean = ts * (1.f / 32768.f);
        float var  = tq * (1.f / 32768.f) - mean * mean;
        stats2[0] = mean; stats2[1] = rsqrtf(var + 1e-5f);
    }
    __syncthreads();
    float mean2 = stats2[0], rstd2 = stats2[1];

    // ---- fused mix2 across 16 warps ----
    float s3 = 0.f, q3 = 0.f;
    for (int yb = 0; yb < 4; ++yb)
        gn_mix_chans<__half, __half>(win, yb * 64 + wid * 4, lane, mean2, rstd2,
                                     tgt3, tgt2, g1w, g1b, ls2, tgt3, s3, q3, true);
#pragma unroll
    for (int off = 16; off; off >>= 1) {
        s3 += __shfl_down_sync(0xffffffffu, s3, off);
        q3 += __shfl_down_sync(0xffffffffu, q3, off);
    }
    if (lane == 0) { ared[wid] = s3; ared[16 + wid] = q3; }
    __syncthreads();
    if (tid == 0) {
        float ts = 0.f, tq = 0.f;
#pragma unroll
        for (int i = 0; i < 16; ++i) { ts += ared[i]; tq += ared[16 + i]; }
        float mean = ts * (1.f / 32768.f);
        float var  = tq * (1.f / 32768.f) - mean * mean;
        stats2[0] = mean; stats2[1] = rsqrtf(var + 1e-5f);
    }
    __syncthreads();
    float mean3 = stats2[0], rstd3 = stats2[1];

    // ---- gn2 apply: hin = gn2(tgt3) -> fp16 (tgt3 is L2-hot) ----
    int p0 = lane * 4;
    for (int yb = 0; yb < 4; ++yb) {
#pragma unroll
        for (int ci = 0; ci < 4; ++ci) {
            int c = yb * 64 + wid * 4 + ci;
            size_t gi = (size_t)win * WSZ + c * 128 + p0;
            float w = g2w[c], bb = g2b[c];
            float4 v = ld4(tgt3 + gi);
            v.x = (v.x - mean3) * rstd3 * w + bb;
            v.y = (v.y - mean3) * rstd3 * w + bb;
            v.z = (v.z - mean3) * rstd3 * w + bb;
            v.w = (v.w - mean3) * rstd3 * w + bb;
            st4h(hinh + gi, v);
        }
    }
}

// ---------------- host orchestration ---------------------------------------
extern "C" void kernel_launch(void* const* d_in, const int* in_sizes, int n_in,
                              void* d_out, int out_size) {
    const float* src  = (const float*)d_in[0];
    const float* qf   = (const float*)d_in[1];
    const float* gn1w = (const float*)d_in[2];
    const float* gn1b = (const float*)d_in[3];
    const float* gn2w = (const float*)d_in[4];
    const float* gn2b = (const float*)d_in[5];
    const float* ls1  = (const float*)d_in[6];
    const float* ls2  = (const float*)d_in[7];
    const float* ls3  = (const float*)d_in[8];
    const float* qw   = (const float*)d_in[9];
    const float* qb   = (const float*)d_in[10];
    const float* kw   = (const float*)d_in[11];
    const float* kb   = (const float*)d_in[12];
    const float* vw   = (const float*)d_in[13];
    const float* vb   = (const float*)d_in[14];
    const float* fc1w = (const float*)d_in[15];
    const float* fc1b = (const float*)d_in[16];
    const float* fc2w = (const float*)d_in[17];
    const float* fc2b = (const float*)d_in[18];
    const float* gnfw = (const float*)d_in[19];
    const float* gnfb = (const float*)d_in[20];
    float* out = (float*)d_out;

    float *tgt, *p0, *p1;
    __half *tgt2h, *tgt3h, *memh, *tgth, *qh, *kh, *vh, *hinh, *hh, *wh;
    cudaGetSymbolAddress((void**)&tgt,  g_tgt);
    cudaGetSymbolAddress((void**)&tgt2h,g_tgt2h);
    cudaGetSymbolAddress((void**)&tgt3h,g_tgt3h);
    cudaGetSymbolAddress((void**)&p0,   g_p0);
    cudaGetSymbolAddress((void**)&p1,   g_p1);
    cudaGetSymbolAddress((void**)&memh, g_memh);
    cudaGetSymbolAddress((void**)&tgth, g_tgth);
    cudaGetSymbolAddress((void**)&qh,   g_qh);
    cudaGetSymbolAddress((void**)&kh,   g_kh);
    cudaGetSymbolAddress((void**)&vh,   g_vh);
    cudaGetSymbolAddress((void**)&hinh, g_hinh);
    cudaGetSymbolAddress((void**)&hh,   g_hh);
    cudaGetSymbolAddress((void**)&wh,   g_wh);

    const int SM_ATTN = 73728;
    const int SM_TC   = 71680;
    cudaFuncSetAttribute(attn_kernel,    cudaFuncAttributeMaxDynamicSharedMemorySize, SM_ATTN);
    cudaFuncSetAttribute(gemm_tc_kernel, cudaFuncAttributeMaxDynamicSharedMemorySize, SM_TC);

    partition_kernel<<<65536, 256>>>(src, qf, memh, tgth, tgt, p0);
    conv_w_all<<<448, 256>>>(qw, kw, vw, fc1w, fc2w, wh);

    for (int l = 0; l < 2; ++l) {
        int lC = l * CDIM;
        size_t lb = (size_t)l * 458752;
        const float* mp = (l == 0) ? p0 : p1;
        int mstride = (l == 0) ? 128 : 16;
        int mnp = (l == 0) ? 64 : 2;
        // merged: QKV gemm (ob<6) + gn_mix1 tgt->tgt2h (ob 6..13)
        gemm_tc_kernel<<<dim3(NW,14), 256, SM_TC>>>(wh + lb,
            tgth, memh, qb + lC, kb + lC, vb + lC,
            nullptr, qh, kh, vh, 256, 0, nullptr, nullptr, nullptr,
            tgt, tgt, mp, mstride, mnp, gn1w + lC, gn1b + lC, ls1 + lC, tgt2h);
        // attn + mix2 + gn2: tgt3h final, hinh = fp16 gn2(tgt3)
        attn_kernel<<<NW, 512, SM_ATTN>>>(qh, kh, vh, tgt2h, tgt3h,
                                          gn1w + lC, gn1b + lC, ls2 + lC,
                                          gn2w + lC, gn2b + lC, hinh);
        // h = gelu(fc1(hin))
        gemm_tc_kernel<<<dim3(NW,4), 256, SM_TC>>>(wh + lb + 196608,
            hinh, nullptr, fc1b + (size_t)l*512, nullptr, nullptr,
            nullptr, hh, nullptr, nullptr, 256, 1, nullptr, nullptr, nullptr,
            nullptr, nullptr, nullptr, 0, 0, nullptr, nullptr, nullptr, nullptr);
        // tgt = tgt3h + ls3*fc2(h)  (+stats -> p1)
        gemm_tc_kernel<<<dim3(NW,2), 256, SM_TC>>>(wh + lb + 327680,
            hh, nullptr, fc2b + lC, nullptr, nullptr,
            tgt, tgth, nullptr, nullptr, 512, 2, tgt3h, ls3 + lC, p1,
            nullptr, nullptr, nullptr, 0, 0, nullptr, nullptr, nullptr, nullptr);
    }

    gn_final_apply<<<dim3(NW,8), 256>>>(tgt, p1, 2, gnfw, gnfb, out);
}